// round 1
// baseline (speedup 1.0000x reference)
#include <cuda_runtime.h>
#include <math.h>

#define B_    8
#define NTOK  2304
#define NROW  (B_*NTOK)      // 18432
#define HK    64
#define KD    16
#define VD    32
#define GM    (NTOK*KD)      // 36864
#define GN    (B_*VD)        // 256
#define GK    NTOK           // 2304

// ---------------- scratch (device globals; no allocations) ----------------
__device__ __align__(256) float g_q[(size_t)NROW*HK];          // 4.7 MB
__device__ __align__(256) float g_k[(size_t)NROW*KD];
__device__ __align__(256) float g_v[(size_t)NROW*VD];
__device__ __align__(256) float g_ksm[(size_t)B_*KD*NTOK];     // softmax(K)
__device__ __align__(256) float g_vt[(size_t)NTOK*GN];         // BN(V) as [m][(b,v)]
__device__ __align__(256) float g_lamc_part[(size_t)144*KD*VD];
__device__ __align__(256) float g_lamc[(size_t)B_*KD*VD];
__device__ __align__(256) float g_qaff[2*HK];                  // scale, shift
__device__ __align__(256) float g_vaff[2*VD];
__device__ __align__(256) float g_lamp[(size_t)GM*GN];         // 37.7 MB

// ---------------- K1: fused q/k/v 1x1 conv (with batch reversal) ----------
__global__ void k_proj(const float* __restrict__ x,
                       const float* __restrict__ Wq,
                       const float* __restrict__ Wk,
                       const float* __restrict__ Wv) {
    extern __shared__ float sm[];
    float* Ws = sm;               // [128][113] transposed weights (padded)
    float* xs = sm + 128*113;     // 4 rows of x
    int t = threadIdx.x;          // 128 threads
    for (int idx = t; idx < 112*128; idx += 128) {
        int o = idx >> 7, c = idx & 127;
        float w;
        if (o < 64)      w = Wq[o*128 + c];
        else if (o < 80) w = Wk[(o-64)*128 + c];
        else             w = Wv[(o-80)*128 + c];
        Ws[c*113 + o] = w;
    }
    __syncthreads();
    int row0 = blockIdx.x * 16;
    for (int rr = 0; rr < 16; rr += 4) {
        for (int cidx = t; cidx < 512; cidx += 128) {
            int r = cidx >> 7, i = cidx & 127;
            xs[cidx] = x[(size_t)(row0+rr+r)*128 + i];
        }
        __syncthreads();
        if (t < 112) {
            float a0=0.f, a1=0.f, a2=0.f, a3=0.f;
            #pragma unroll 8
            for (int i = 0; i < 128; i++) {
                float w = Ws[i*113 + t];
                a0 += w*xs[i]; a1 += w*xs[128+i]; a2 += w*xs[256+i]; a3 += w*xs[384+i];
            }
            float acc[4] = {a0,a1,a2,a3};
            #pragma unroll
            for (int r2 = 0; r2 < 4; r2++) {
                int row = row0 + rr + r2;
                int bs = row / NTOK, n = row - bs*NTOK;
                if (t < 64) {
                    g_q[(size_t)row*64 + t] = acc[r2];
                } else {
                    int drow = ((bs + 4) & 7)*NTOK + n;   // frame reversal
                    if (t < 80) g_k[(size_t)drow*16 + (t-64)] = acc[r2];
                    else        g_v[(size_t)drow*32 + (t-80)] = acc[r2];
                }
            }
        }
        __syncthreads();
    }
}

// ---------------- K2: BN batch stats -> affine (scale, shift) -------------
__global__ void k_stats(const float* __restrict__ gq, const float* __restrict__ bq,
                        const float* __restrict__ gv, const float* __restrict__ bv) {
    __shared__ float s1[256], s2[256];
    int ch = blockIdx.x, t = threadIdx.x;
    float a = 0.f, b2 = 0.f;
    if (ch < 64) {
        for (int r = t; r < NROW; r += 256) { float xv = g_q[(size_t)r*64 + ch]; a += xv; b2 += xv*xv; }
    } else {
        int c = ch - 64;
        for (int r = t; r < NROW; r += 256) { float xv = g_v[(size_t)r*32 + c]; a += xv; b2 += xv*xv; }
    }
    s1[t] = a; s2[t] = b2; __syncthreads();
    for (int s = 128; s > 0; s >>= 1) {
        if (t < s) { s1[t] += s1[t+s]; s2[t] += s2[t+s]; }
        __syncthreads();
    }
    if (t == 0) {
        float mu  = s1[0] / (float)NROW;
        float var = s2[0] / (float)NROW - mu*mu;     // biased
        if (ch < 64) {
            float sc = gq[ch] * rsqrtf(var + 1e-5f);
            g_qaff[ch] = sc; g_qaff[64+ch] = bq[ch] - mu*sc;
        } else {
            int c = ch - 64;
            float sc = gv[c] * rsqrtf(var + 1e-5f);
            g_vaff[c] = sc; g_vaff[32+c] = bv[c] - mu*sc;
        }
    }
}

// ---------------- K3: softmax over m per (b, kd) --------------------------
__global__ void k_softmax() {
    __shared__ float red[256];
    int bk = blockIdx.x;               // b*16 + kd
    int kd = bk & 15, b = bk >> 4;
    int t = threadIdx.x;
    size_t base = (size_t)b*NTOK*16 + kd;
    float mx = -1e30f;
    for (int m = t; m < NTOK; m += 256) mx = fmaxf(mx, g_k[base + (size_t)m*16]);
    red[t] = mx; __syncthreads();
    for (int s = 128; s > 0; s >>= 1) { if (t < s) red[t] = fmaxf(red[t], red[t+s]); __syncthreads(); }
    mx = red[0]; __syncthreads();
    float* dst = g_ksm + (size_t)bk*NTOK;
    float sum = 0.f;
    for (int m = t; m < NTOK; m += 256) {
        float e = expf(g_k[base + (size_t)m*16] - mx);
        dst[m] = e; sum += e;
    }
    red[t] = sum; __syncthreads();
    for (int s = 128; s > 0; s >>= 1) { if (t < s) red[t] += red[t+s]; __syncthreads(); }
    float inv = 1.0f / red[0];
    for (int m = t; m < NTOK; m += 256) dst[m] *= inv;
}

// ---------------- K3b: BN(V) transposed to [m][(b,v)] ---------------------
__global__ void k_vt() {
    int idx = blockIdx.x*256 + threadIdx.x;      // exactly NTOK*256
    int m = idx >> 8, c = idx & 255;
    int b = c >> 5, v = c & 31;
    float xv = g_v[((size_t)b*NTOK + m)*32 + v];
    g_vt[idx] = xv * g_vaff[v] + g_vaff[32+v];
}

// ---------------- K4: content lambda lamc (partial + reduce) --------------
__global__ void k_lamc_part() {
    __shared__ float Ks[16*128];
    __shared__ float Vs[128*32];
    int b = blockIdx.x / 18, mc = blockIdx.x - b*18;
    int m0 = mc * 128;
    int t = threadIdx.x;   // 512
    for (int i = t; i < 2048; i += 512) { int k = i>>7, mm = i&127; Ks[i] = g_ksm[(size_t)(b*16+k)*NTOK + m0+mm]; }
    for (int i = t; i < 4096; i += 512) { int mm = i>>5, v = i&31;  Vs[i] = g_vt[(size_t)(m0+mm)*256 + b*32 + v]; }
    __syncthreads();
    int k = t >> 5, v = t & 31;
    float acc = 0.f;
    #pragma unroll 8
    for (int mm = 0; mm < 128; mm++) acc += Ks[k*128+mm] * Vs[mm*32+v];
    g_lamc_part[(size_t)blockIdx.x*512 + t] = acc;
}
__global__ void k_lamc_red() {
    int b = blockIdx.x, t = threadIdx.x;   // 8 x 512
    float s = 0.f;
    for (int mc = 0; mc < 18; mc++) s += g_lamc_part[(size_t)(b*18+mc)*512 + t];
    g_lamc[b*512 + t] = s;
}

// ---------------- K5: THE BIG GEMM (fused rel-pos gather) -----------------
// C[(n,k), (b,v)] = sum_m R[drow(n,m), dcol(n,m), k] * Vt[m][(b,v)]
// M=36864, N=256, K=2304; tiles 128x128x16, 8x8 per thread.
__global__ void k_lamp(const float* __restrict__ R) {
    __shared__ __align__(16) float As[16*128];
    __shared__ __align__(16) float Bs[16*128];
    int t = threadIdx.x;              // 256
    int bn0 = blockIdx.x * 128;
    int nbase = blockIdx.y * 8;       // 8 n-values per 128-row tile
    // A-gather role: 2 threads per (n_loc, r) pair, 8 floats each (k half)
    int gidx = t >> 1, half = t & 1;
    int n_loc = gidx >> 4, r = gidx & 15;
    int n = nbase + n_loc;
    int n_row = n / 48, n_col = n - n_row*48;
    int acol = n_loc*16 + half*8;
    // B-load role
    int rb = t >> 4, cb = (t & 15) * 8;
    int ty = t >> 4, tx = t & 15;
    float acc[8][8];
    #pragma unroll
    for (int i = 0; i < 8; i++)
        #pragma unroll
        for (int j = 0; j < 8; j++) acc[i][j] = 0.f;

    for (int k0 = 0; k0 < GK; k0 += 16) {
        int m = k0 + r;
        int m_row = m / 48; int m_col = m - m_row*48;
        int off = (((m_row - n_row + 47)*95 + (m_col - n_col + 47)) << 4) + (half << 3);
        const float4* R4 = (const float4*)(R + off);
        float4 av0 = R4[0], av1 = R4[1];
        *(float4*)&As[r*128 + acol]     = av0;
        *(float4*)&As[r*128 + acol + 4] = av1;
        const float* bp = g_vt + (size_t)(k0 + rb)*256 + bn0 + cb;
        *(float4*)&Bs[rb*128 + cb]     = *(const float4*)bp;
        *(float4*)&Bs[rb*128 + cb + 4] = *(const float4*)(bp + 4);
        __syncthreads();
        #pragma unroll
        for (int kk = 0; kk < 16; kk++) {
            float4 a0 = *(const float4*)&As[kk*128 + ty*8];
            float4 a1 = *(const float4*)&As[kk*128 + ty*8 + 4];
            float4 b0 = *(const float4*)&Bs[kk*128 + tx*8];
            float4 b1 = *(const float4*)&Bs[kk*128 + tx*8 + 4];
            float a[8]  = {a0.x,a0.y,a0.z,a0.w,a1.x,a1.y,a1.z,a1.w};
            float bb[8] = {b0.x,b0.y,b0.z,b0.w,b1.x,b1.y,b1.z,b1.w};
            #pragma unroll
            for (int i = 0; i < 8; i++)
                #pragma unroll
                for (int j = 0; j < 8; j++) acc[i][j] += a[i]*bb[j];
        }
        __syncthreads();
    }
    int bm0 = blockIdx.y * 128;
    #pragma unroll
    for (int i = 0; i < 8; i++) {
        size_t o = (size_t)(bm0 + ty*8 + i)*256 + bn0 + tx*8;
        *(float4*)&g_lamp[o]     = make_float4(acc[i][0],acc[i][1],acc[i][2],acc[i][3]);
        *(float4*)&g_lamp[o + 4] = make_float4(acc[i][4],acc[i][5],acc[i][6],acc[i][7]);
    }
}

// ---------------- K6: consumers -> appearance + motion --------------------
__global__ void k_out(const float* __restrict__ cor,
                      const float* __restrict__ Wce, const float* __restrict__ bce,
                      const float* __restrict__ Wcc, const float* __restrict__ Wmp,
                      const float* __restrict__ bmp,
                      float* __restrict__ app, float* __restrict__ mot) {
    extern __shared__ float sm[];
    float* WccT  = sm;            // [128][65]  (padded, c-major)
    float* WmpT  = sm + 8320;     // [64][129]
    float* WceS  = sm + 16576;    // 128
    float* bceS  = sm + 16704;    // 64
    float* bmpS  = sm + 16768;    // 128
    float* lamcS = sm + 16896;    // 512
    float* grp   = sm + 17408;    // 2 groups x 832
    int t = threadIdx.x;          // 256: two 128-thread groups, 2 rows at a time
    int g = t >> 7, t1 = t & 127;
    int b = (blockIdx.x * 8) / NTOK;    // 8 | 2304, so b constant per block

    for (int i = t; i < 8192; i += 256) { int o = i>>7, c = i&127; WccT[c*65 + o]  = Wcc[i]; }
    for (int i = t; i < 8192; i += 256) { int o = i>>6, c = i&63;  WmpT[c*129 + o] = Wmp[i]; }
    if (t < 128) WceS[t] = Wce[t];
    if (t < 64)  bceS[t] = bce[t];
    if (t < 128) bmpS[t] = bmp[t];
    for (int i = t; i < 512; i += 256) lamcS[i] = g_lamc[b*512 + i];
    __syncthreads();

    float* Qn   = grp + g*832;
    float* ceS  = Qn + 64;
    float* Ltot = ceS + 64;    // 512
    float* crow = Ltot + 512;  // 128
    float* dif  = crow + 128;  // 64

    for (int it = 0; it < 4; it++) {
        int row = blockIdx.x*8 + it*2 + g;     // global (b, n) row
        int n = row - b*NTOK;
        for (int i = t1; i < 512; i += 128) {
            int k = i >> 5, v = i & 31;
            Ltot[i] = lamcS[i] + g_lamp[(size_t)(n*16 + k)*256 + b*32 + v];
        }
        if (t1 < 64) {
            Qn[t1] = g_q[(size_t)row*64 + t1] * g_qaff[t1] + g_qaff[64+t1];
        } else {
            int o = t1 - 64;
            float c0 = cor[(size_t)row*2], c1 = cor[(size_t)row*2 + 1];
            ceS[o] = c0*WceS[o*2] + c1*WceS[o*2+1] + bceS[o];
        }
        __syncthreads();
        {
            int h = t1 >> 5, v = t1 & 31;
            float y = 0.f, cr = 0.f;
            #pragma unroll
            for (int k = 0; k < 16; k++) {
                float a = Ltot[k*32 + v];
                y  += Qn[h*16 + k]  * a;
                cr += ceS[h*16 + k] * a;
            }
            app[(size_t)row*128 + t1] = y;
            crow[t1] = cr;
        }
        __syncthreads();
        if (t1 < 64) {
            float s = 0.f;
            #pragma unroll 4
            for (int c = 0; c < 128; c++) s += crow[c] * WccT[c*65 + t1];
            dif[t1] = s - ceS[t1];
        }
        __syncthreads();
        {
            float s = bmpS[t1];
            #pragma unroll 4
            for (int c = 0; c < 64; c++) s += dif[c] * WmpT[c*129 + t1];
            mot[(size_t)row*128 + t1] = s;
        }
        __syncthreads();
    }
}

// ---------------- launch ---------------------------------------------------
extern "C" void kernel_launch(void* const* d_in, const int* in_sizes, int n_in,
                              void* d_out, int out_size) {
    const float* x   = (const float*)d_in[0];
    const float* cor = (const float*)d_in[1];
    const float* Wq  = (const float*)d_in[2];
    const float* Wk  = (const float*)d_in[3];
    const float* Wv  = (const float*)d_in[4];
    const float* Wce = (const float*)d_in[5];
    const float* bce = (const float*)d_in[6];
    const float* Wcc = (const float*)d_in[7];
    const float* Wmp = (const float*)d_in[8];
    const float* bmp = (const float*)d_in[9];
    const float* gq  = (const float*)d_in[10];
    const float* bq  = (const float*)d_in[11];
    const float* gv  = (const float*)d_in[12];
    const float* bv  = (const float*)d_in[13];
    const float* rpe = (const float*)d_in[14];
    float* app = (float*)d_out;
    float* mot = app + (size_t)NROW*128;

    cudaFuncSetAttribute(k_proj, cudaFuncAttributeMaxDynamicSharedMemorySize, (128*113 + 512)*4);
    cudaFuncSetAttribute(k_out,  cudaFuncAttributeMaxDynamicSharedMemorySize, 19072*4);

    k_proj<<<NROW/16, 128, (128*113 + 512)*4>>>(x, Wq, Wk, Wv);
    k_stats<<<96, 256>>>(gq, bq, gv, bv);
    k_softmax<<<128, 256>>>();
    k_vt<<<NTOK, 256>>>();
    k_lamc_part<<<144, 512>>>();
    k_lamc_red<<<8, 512>>>();
    k_lamp<<<dim3(2, 288), 256>>>(rpe);
    k_out<<<NROW/8, 256, 19072*4>>>(cor, Wce, bce, Wcc, Wmp, bmp, app, mot);
}

// round 2
// speedup vs baseline: 1.0003x; 1.0003x over previous
#include <cuda_runtime.h>
#include <math.h>

#define B_    8
#define NTOK  2304
#define NROW  (B_*NTOK)      // 18432
#define HK    64
#define KD    16
#define VD    32
#define GM    (NTOK*KD)      // 36864
#define GN    (B_*VD)        // 256
#define GK    NTOK           // 2304

// ---------------- scratch (device globals; no allocations) ----------------
__device__ __align__(256) float g_q[(size_t)NROW*HK];          // 4.7 MB
__device__ __align__(256) float g_k[(size_t)NROW*KD];
__device__ __align__(256) float g_v[(size_t)NROW*VD];
__device__ __align__(256) float g_ksm[(size_t)B_*KD*NTOK];     // softmax(K)
__device__ __align__(256) float g_vt[(size_t)NTOK*GN];         // BN(V) as [m][(b,v)]
__device__ __align__(256) float g_lamc_part[(size_t)144*KD*VD];
__device__ __align__(256) float g_lamc[(size_t)B_*KD*VD];
__device__ __align__(256) float g_qaff[2*HK];                  // scale, shift
__device__ __align__(256) float g_vaff[2*VD];
__device__ __align__(256) float g_lamp[(size_t)GM*GN];         // 37.7 MB

// ---------------- K1: fused q/k/v 1x1 conv (with batch reversal) ----------
__global__ void k_proj(const float* __restrict__ x,
                       const float* __restrict__ Wq,
                       const float* __restrict__ Wk,
                       const float* __restrict__ Wv) {
    extern __shared__ float sm[];
    float* Ws = sm;               // [128][113] transposed weights (padded)
    float* xs = sm + 128*113;     // 4 rows of x
    int t = threadIdx.x;          // 128 threads
    for (int idx = t; idx < 112*128; idx += 128) {
        int o = idx >> 7, c = idx & 127;
        float w;
        if (o < 64)      w = Wq[o*128 + c];
        else if (o < 80) w = Wk[(o-64)*128 + c];
        else             w = Wv[(o-80)*128 + c];
        Ws[c*113 + o] = w;
    }
    __syncthreads();
    int row0 = blockIdx.x * 16;
    for (int rr = 0; rr < 16; rr += 4) {
        for (int cidx = t; cidx < 512; cidx += 128) {
            int r = cidx >> 7, i = cidx & 127;
            xs[cidx] = x[(size_t)(row0+rr+r)*128 + i];
        }
        __syncthreads();
        if (t < 112) {
            float a0=0.f, a1=0.f, a2=0.f, a3=0.f;
            #pragma unroll 8
            for (int i = 0; i < 128; i++) {
                float w = Ws[i*113 + t];
                a0 += w*xs[i]; a1 += w*xs[128+i]; a2 += w*xs[256+i]; a3 += w*xs[384+i];
            }
            float acc[4] = {a0,a1,a2,a3};
            #pragma unroll
            for (int r2 = 0; r2 < 4; r2++) {
                int row = row0 + rr + r2;
                int bs = row / NTOK, n = row - bs*NTOK;
                if (t < 64) {
                    g_q[(size_t)row*64 + t] = acc[r2];
                } else {
                    int drow = ((bs + 4) & 7)*NTOK + n;   // frame reversal
                    if (t < 80) g_k[(size_t)drow*16 + (t-64)] = acc[r2];
                    else        g_v[(size_t)drow*32 + (t-80)] = acc[r2];
                }
            }
        }
        __syncthreads();
    }
}

// ---------------- K2: BN batch stats -> affine (scale, shift) -------------
__global__ void k_stats(const float* __restrict__ gq, const float* __restrict__ bq,
                        const float* __restrict__ gv, const float* __restrict__ bv) {
    __shared__ float s1[256], s2[256];
    int ch = blockIdx.x, t = threadIdx.x;
    float a = 0.f, b2 = 0.f;
    if (ch < 64) {
        for (int r = t; r < NROW; r += 256) { float xv = g_q[(size_t)r*64 + ch]; a += xv; b2 += xv*xv; }
    } else {
        int c = ch - 64;
        for (int r = t; r < NROW; r += 256) { float xv = g_v[(size_t)r*32 + c]; a += xv; b2 += xv*xv; }
    }
    s1[t] = a; s2[t] = b2; __syncthreads();
    for (int s = 128; s > 0; s >>= 1) {
        if (t < s) { s1[t] += s1[t+s]; s2[t] += s2[t+s]; }
        __syncthreads();
    }
    if (t == 0) {
        float mu  = s1[0] / (float)NROW;
        float var = s2[0] / (float)NROW - mu*mu;     // biased
        if (ch < 64) {
            float sc = gq[ch] * rsqrtf(var + 1e-5f);
            g_qaff[ch] = sc; g_qaff[64+ch] = bq[ch] - mu*sc;
        } else {
            int c = ch - 64;
            float sc = gv[c] * rsqrtf(var + 1e-5f);
            g_vaff[c] = sc; g_vaff[32+c] = bv[c] - mu*sc;
        }
    }
}

// ---------------- K3: softmax over m per (b, kd) --------------------------
__global__ void k_softmax() {
    __shared__ float red[256];
    int bk = blockIdx.x;               // b*16 + kd
    int kd = bk & 15, b = bk >> 4;
    int t = threadIdx.x;
    size_t base = (size_t)b*NTOK*16 + kd;
    float mx = -1e30f;
    for (int m = t; m < NTOK; m += 256) mx = fmaxf(mx, g_k[base + (size_t)m*16]);
    red[t] = mx; __syncthreads();
    for (int s = 128; s > 0; s >>= 1) { if (t < s) red[t] = fmaxf(red[t], red[t+s]); __syncthreads(); }
    mx = red[0]; __syncthreads();
    float* dst = g_ksm + (size_t)bk*NTOK;
    float sum = 0.f;
    for (int m = t; m < NTOK; m += 256) {
        float e = expf(g_k[base + (size_t)m*16] - mx);
        dst[m] = e; sum += e;
    }
    red[t] = sum; __syncthreads();
    for (int s = 128; s > 0; s >>= 1) { if (t < s) red[t] += red[t+s]; __syncthreads(); }
    float inv = 1.0f / red[0];
    for (int m = t; m < NTOK; m += 256) dst[m] *= inv;
}

// ---------------- K3b: BN(V) transposed to [m][(b,v)] ---------------------
__global__ void k_vt() {
    int idx = blockIdx.x*256 + threadIdx.x;      // exactly NTOK*256
    int m = idx >> 8, c = idx & 255;
    int b = c >> 5, v = c & 31;
    float xv = g_v[((size_t)b*NTOK + m)*32 + v];
    g_vt[idx] = xv * g_vaff[v] + g_vaff[32+v];
}

// ---------------- K4: content lambda lamc (partial + reduce) --------------
__global__ void k_lamc_part() {
    __shared__ float Ks[16*128];
    __shared__ float Vs[128*32];
    int b = blockIdx.x / 18, mc = blockIdx.x - b*18;
    int m0 = mc * 128;
    int t = threadIdx.x;   // 512
    for (int i = t; i < 2048; i += 512) { int k = i>>7, mm = i&127; Ks[i] = g_ksm[(size_t)(b*16+k)*NTOK + m0+mm]; }
    for (int i = t; i < 4096; i += 512) { int mm = i>>5, v = i&31;  Vs[i] = g_vt[(size_t)(m0+mm)*256 + b*32 + v]; }
    __syncthreads();
    int k = t >> 5, v = t & 31;
    float acc = 0.f;
    #pragma unroll 8
    for (int mm = 0; mm < 128; mm++) acc += Ks[k*128+mm] * Vs[mm*32+v];
    g_lamc_part[(size_t)blockIdx.x*512 + t] = acc;
}
__global__ void k_lamc_red() {
    int b = blockIdx.x, t = threadIdx.x;   // 8 x 512
    float s = 0.f;
    for (int mc = 0; mc < 18; mc++) s += g_lamc_part[(size_t)(b*18+mc)*512 + t];
    g_lamc[b*512 + t] = s;
}

// ---------------- K5: THE BIG GEMM (fused rel-pos gather) -----------------
// C[(n,k), (b,v)] = sum_m R[drow(n,m), dcol(n,m), k] * Vt[m][(b,v)]
// M=36864, N=256, K=2304; tiles 128x128x16, 8x8 per thread.
__global__ void k_lamp(const float* __restrict__ R) {
    __shared__ __align__(16) float As[16*128];
    __shared__ __align__(16) float Bs[16*128];
    int t = threadIdx.x;              // 256
    int bn0 = blockIdx.x * 128;
    int nbase = blockIdx.y * 8;       // 8 n-values per 128-row tile
    // A-gather role: 2 threads per (n_loc, r) pair, 8 floats each (k half)
    int gidx = t >> 1, half = t & 1;
    int n_loc = gidx >> 4, r = gidx & 15;
    int n = nbase + n_loc;
    int n_row = n / 48, n_col = n - n_row*48;
    int acol = n_loc*16 + half*8;
    // B-load role
    int rb = t >> 4, cb = (t & 15) * 8;
    int ty = t >> 4, tx = t & 15;
    float acc[8][8];
    #pragma unroll
    for (int i = 0; i < 8; i++)
        #pragma unroll
        for (int j = 0; j < 8; j++) acc[i][j] = 0.f;

    for (int k0 = 0; k0 < GK; k0 += 16) {
        int m = k0 + r;
        int m_row = m / 48; int m_col = m - m_row*48;
        int off = (((m_row - n_row + 47)*95 + (m_col - n_col + 47)) << 4) + (half << 3);
        const float4* R4 = (const float4*)(R + off);
        float4 av0 = R4[0], av1 = R4[1];
        *(float4*)&As[r*128 + acol]     = av0;
        *(float4*)&As[r*128 + acol + 4] = av1;
        const float* bp = g_vt + (size_t)(k0 + rb)*256 + bn0 + cb;
        *(float4*)&Bs[rb*128 + cb]     = *(const float4*)bp;
        *(float4*)&Bs[rb*128 + cb + 4] = *(const float4*)(bp + 4);
        __syncthreads();
        #pragma unroll
        for (int kk = 0; kk < 16; kk++) {
            float4 a0 = *(const float4*)&As[kk*128 + ty*8];
            float4 a1 = *(const float4*)&As[kk*128 + ty*8 + 4];
            float4 b0 = *(const float4*)&Bs[kk*128 + tx*8];
            float4 b1 = *(const float4*)&Bs[kk*128 + tx*8 + 4];
            float a[8]  = {a0.x,a0.y,a0.z,a0.w,a1.x,a1.y,a1.z,a1.w};
            float bb[8] = {b0.x,b0.y,b0.z,b0.w,b1.x,b1.y,b1.z,b1.w};
            #pragma unroll
            for (int i = 0; i < 8; i++)
                #pragma unroll
                for (int j = 0; j < 8; j++) acc[i][j] += a[i]*bb[j];
        }
        __syncthreads();
    }
    int bm0 = blockIdx.y * 128;
    #pragma unroll
    for (int i = 0; i < 8; i++) {
        size_t o = (size_t)(bm0 + ty*8 + i)*256 + bn0 + tx*8;
        *(float4*)&g_lamp[o]     = make_float4(acc[i][0],acc[i][1],acc[i][2],acc[i][3]);
        *(float4*)&g_lamp[o + 4] = make_float4(acc[i][4],acc[i][5],acc[i][6],acc[i][7]);
    }
}

// ---------------- K6: consumers -> appearance + motion --------------------
__global__ void k_out(const float* __restrict__ cor,
                      const float* __restrict__ Wce, const float* __restrict__ bce,
                      const float* __restrict__ Wcc, const float* __restrict__ Wmp,
                      const float* __restrict__ bmp,
                      float* __restrict__ app, float* __restrict__ mot) {
    extern __shared__ float sm[];
    float* WccT  = sm;            // [128][65]  (padded, c-major)
    float* WmpT  = sm + 8320;     // [64][129]
    float* WceS  = sm + 16576;    // 128
    float* bceS  = sm + 16704;    // 64
    float* bmpS  = sm + 16768;    // 128
    float* lamcS = sm + 16896;    // 512
    float* grp   = sm + 17408;    // 2 groups x 832
    int t = threadIdx.x;          // 256: two 128-thread groups, 2 rows at a time
    int g = t >> 7, t1 = t & 127;
    int b = (blockIdx.x * 8) / NTOK;    // 8 | 2304, so b constant per block

    for (int i = t; i < 8192; i += 256) { int o = i>>7, c = i&127; WccT[c*65 + o]  = Wcc[i]; }
    for (int i = t; i < 8192; i += 256) { int o = i>>6, c = i&63;  WmpT[c*129 + o] = Wmp[i]; }
    if (t < 128) WceS[t] = Wce[t];
    if (t < 64)  bceS[t] = bce[t];
    if (t < 128) bmpS[t] = bmp[t];
    for (int i = t; i < 512; i += 256) lamcS[i] = g_lamc[b*512 + i];
    __syncthreads();

    float* Qn   = grp + g*832;
    float* ceS  = Qn + 64;
    float* Ltot = ceS + 64;    // 512
    float* crow = Ltot + 512;  // 128
    float* dif  = crow + 128;  // 64

    for (int it = 0; it < 4; it++) {
        int row = blockIdx.x*8 + it*2 + g;     // global (b, n) row
        int n = row - b*NTOK;
        for (int i = t1; i < 512; i += 128) {
            int k = i >> 5, v = i & 31;
            Ltot[i] = lamcS[i] + g_lamp[(size_t)(n*16 + k)*256 + b*32 + v];
        }
        if (t1 < 64) {
            Qn[t1] = g_q[(size_t)row*64 + t1] * g_qaff[t1] + g_qaff[64+t1];
        } else {
            int o = t1 - 64;
            float c0 = cor[(size_t)row*2], c1 = cor[(size_t)row*2 + 1];
            ceS[o] = c0*WceS[o*2] + c1*WceS[o*2+1] + bceS[o];
        }
        __syncthreads();
        {
            int h = t1 >> 5, v = t1 & 31;
            float y = 0.f, cr = 0.f;
            #pragma unroll
            for (int k = 0; k < 16; k++) {
                float a = Ltot[k*32 + v];
                y  += Qn[h*16 + k]  * a;
                cr += ceS[h*16 + k] * a;
            }
            app[(size_t)row*128 + t1] = y;
            crow[t1] = cr;
        }
        __syncthreads();
        if (t1 < 64) {
            float s = 0.f;
            #pragma unroll 4
            for (int c = 0; c < 128; c++) s += crow[c] * WccT[c*65 + t1];
            dif[t1] = s - ceS[t1];
        }
        __syncthreads();
        {
            float s = bmpS[t1];
            #pragma unroll 4
            for (int c = 0; c < 64; c++) s += dif[c] * WmpT[c*129 + t1];
            mot[(size_t)row*128 + t1] = s;
        }
        __syncthreads();
    }
}

// ---------------- launch ---------------------------------------------------
extern "C" void kernel_launch(void* const* d_in, const int* in_sizes, int n_in,
                              void* d_out, int out_size) {
    const float* x   = (const float*)d_in[0];
    const float* cor = (const float*)d_in[1];
    const float* Wq  = (const float*)d_in[2];
    const float* Wk  = (const float*)d_in[3];
    const float* Wv  = (const float*)d_in[4];
    const float* Wce = (const float*)d_in[5];
    const float* bce = (const float*)d_in[6];
    const float* Wcc = (const float*)d_in[7];
    const float* Wmp = (const float*)d_in[8];
    const float* bmp = (const float*)d_in[9];
    const float* gq  = (const float*)d_in[10];
    const float* bq  = (const float*)d_in[11];
    const float* gv  = (const float*)d_in[12];
    const float* bv  = (const float*)d_in[13];
    const float* rpe = (const float*)d_in[14];
    float* app = (float*)d_out;
    float* mot = app + (size_t)NROW*128;

    cudaFuncSetAttribute(k_proj, cudaFuncAttributeMaxDynamicSharedMemorySize, (128*113 + 512)*4);
    cudaFuncSetAttribute(k_out,  cudaFuncAttributeMaxDynamicSharedMemorySize, 19072*4);

    k_proj<<<NROW/16, 128, (128*113 + 512)*4>>>(x, Wq, Wk, Wv);
    k_stats<<<96, 256>>>(gq, bq, gv, bv);
    k_softmax<<<128, 256>>>();
    k_vt<<<NTOK, 256>>>();
    k_lamc_part<<<144, 512>>>();
    k_lamc_red<<<8, 512>>>();
    k_lamp<<<dim3(2, 288), 256>>>(rpe);
    k_out<<<NROW/8, 256, 19072*4>>>(cor, Wce, bce, Wcc, Wmp, bmp, app, mot);
}

// round 4
// speedup vs baseline: 1.5269x; 1.5264x over previous
#include <cuda_runtime.h>
#include <cuda_bf16.h>
#include <math.h>
#include <stdint.h>

#define B_    8
#define NTOK  2304
#define NROW  (B_*NTOK)      // 18432
#define HK    64
#define KD    16
#define VD    32
#define GM    (NTOK*KD)      // 36864
#define GN    (B_*VD)        // 256
#define GK    NTOK           // 2304

// ---------------- scratch (device globals; no allocations) ----------------
__device__ __align__(256) float g_q[(size_t)NROW*HK];
__device__ __align__(256) float g_k[(size_t)NROW*KD];
__device__ __align__(256) float g_v[(size_t)NROW*VD];
__device__ __align__(256) float g_ksm[(size_t)B_*KD*NTOK];
__device__ __align__(256) float g_vt[(size_t)NTOK*GN];                 // BN(V) [m][(b,v)] fp32
__device__ __align__(256) __nv_bfloat16 g_vthi[(size_t)GN*NTOK];       // [(b,v)][m] bf16 hi
__device__ __align__(256) __nv_bfloat16 g_vtlo[(size_t)GN*NTOK];       // [(b,v)][m] bf16 lo
__device__ __align__(256) float g_lamc_part[(size_t)144*KD*VD];
__device__ __align__(256) float g_lamc[(size_t)B_*KD*VD];
__device__ __align__(256) float g_qaff[2*HK];
__device__ __align__(256) float g_vaff[2*VD];
__device__ __align__(256) float g_lamp[(size_t)GM*GN];

// ---------------- portable PTX helpers (no 'a'-features) -------------------
__device__ __forceinline__ uint32_t smem_u32(const void* p) {
    uint32_t a;
    asm("{ .reg .u64 t; cvta.to.shared.u64 t, %1; cvt.u32.u64 %0, t; }" : "=r"(a) : "l"(p));
    return a;
}
__device__ __forceinline__ void ldmx4(uint32_t* r, uint32_t addr) {
    asm volatile("ldmatrix.sync.aligned.m8n8.x4.shared.b16 {%0,%1,%2,%3}, [%4];"
        : "=r"(r[0]), "=r"(r[1]), "=r"(r[2]), "=r"(r[3]) : "r"(addr));
}
__device__ __forceinline__ void mma16816(float* d, const uint32_t* a, uint32_t b0, uint32_t b1) {
    asm volatile("mma.sync.aligned.m16n8k16.row.col.f32.bf16.bf16.f32 "
        "{%0,%1,%2,%3}, {%4,%5,%6,%7}, {%8,%9}, {%0,%1,%2,%3};"
        : "+f"(d[0]), "+f"(d[1]), "+f"(d[2]), "+f"(d[3])
        : "r"(a[0]), "r"(a[1]), "r"(a[2]), "r"(a[3]), "r"(b0), "r"(b1));
}
__device__ __forceinline__ void cp16(uint32_t saddr, const void* g) {
    asm volatile("cp.async.cg.shared.global [%0], [%1], 16;" :: "r"(saddr), "l"(g));
}
#define CP_COMMIT() asm volatile("cp.async.commit_group;" ::: "memory")
#define CP_WAIT1()  asm volatile("cp.async.wait_group 1;" ::: "memory")
#define CP_WAIT0()  asm volatile("cp.async.wait_group 0;" ::: "memory")

// ---------------- K1: fused q/k/v 1x1 conv (with batch reversal) ----------
__global__ void k_proj(const float* __restrict__ x,
                       const float* __restrict__ Wq,
                       const float* __restrict__ Wk,
                       const float* __restrict__ Wv) {
    extern __shared__ float sm[];
    float* Ws = sm;
    float* xs = sm + 128*113;
    int t = threadIdx.x;
    for (int idx = t; idx < 112*128; idx += 128) {
        int o = idx >> 7, c = idx & 127;
        float w;
        if (o < 64)      w = Wq[o*128 + c];
        else if (o < 80) w = Wk[(o-64)*128 + c];
        else             w = Wv[(o-80)*128 + c];
        Ws[c*113 + o] = w;
    }
    __syncthreads();
    int row0 = blockIdx.x * 16;
    for (int rr = 0; rr < 16; rr += 4) {
        for (int cidx = t; cidx < 512; cidx += 128) {
            int r = cidx >> 7, i = cidx & 127;
            xs[cidx] = x[(size_t)(row0+rr+r)*128 + i];
        }
        __syncthreads();
        if (t < 112) {
            float a0=0.f, a1=0.f, a2=0.f, a3=0.f;
            #pragma unroll 8
            for (int i = 0; i < 128; i++) {
                float w = Ws[i*113 + t];
                a0 += w*xs[i]; a1 += w*xs[128+i]; a2 += w*xs[256+i]; a3 += w*xs[384+i];
            }
            float acc[4] = {a0,a1,a2,a3};
            #pragma unroll
            for (int r2 = 0; r2 < 4; r2++) {
                int row = row0 + rr + r2;
                int bs = row / NTOK, n = row - bs*NTOK;
                if (t < 64) {
                    g_q[(size_t)row*64 + t] = acc[r2];
                } else {
                    int drow = ((bs + 4) & 7)*NTOK + n;
                    if (t < 80) g_k[(size_t)drow*16 + (t-64)] = acc[r2];
                    else        g_v[(size_t)drow*32 + (t-80)] = acc[r2];
                }
            }
        }
        __syncthreads();
    }
}

// ---------------- K2: BN batch stats ---------------------------------------
__global__ void k_stats(const float* __restrict__ gq, const float* __restrict__ bq,
                        const float* __restrict__ gv, const float* __restrict__ bv) {
    __shared__ float s1[256], s2[256];
    int ch = blockIdx.x, t = threadIdx.x;
    float a = 0.f, b2 = 0.f;
    if (ch < 64) {
        for (int r = t; r < NROW; r += 256) { float xv = g_q[(size_t)r*64 + ch]; a += xv; b2 += xv*xv; }
    } else {
        int c = ch - 64;
        for (int r = t; r < NROW; r += 256) { float xv = g_v[(size_t)r*32 + c]; a += xv; b2 += xv*xv; }
    }
    s1[t] = a; s2[t] = b2; __syncthreads();
    for (int s = 128; s > 0; s >>= 1) {
        if (t < s) { s1[t] += s1[t+s]; s2[t] += s2[t+s]; }
        __syncthreads();
    }
    if (t == 0) {
        float mu  = s1[0] / (float)NROW;
        float var = s2[0] / (float)NROW - mu*mu;
        if (ch < 64) {
            float sc = gq[ch] * rsqrtf(var + 1e-5f);
            g_qaff[ch] = sc; g_qaff[64+ch] = bq[ch] - mu*sc;
        } else {
            int c = ch - 64;
            float sc = gv[c] * rsqrtf(var + 1e-5f);
            g_vaff[c] = sc; g_vaff[32+c] = bv[c] - mu*sc;
        }
    }
}

// ---------------- K3: softmax over m per (b, kd) ---------------------------
__global__ void k_softmax() {
    __shared__ float red[256];
    int bk = blockIdx.x;
    int kd = bk & 15, b = bk >> 4;
    int t = threadIdx.x;
    size_t base = (size_t)b*NTOK*16 + kd;
    float mx = -1e30f;
    for (int m = t; m < NTOK; m += 256) mx = fmaxf(mx, g_k[base + (size_t)m*16]);
    red[t] = mx; __syncthreads();
    for (int s = 128; s > 0; s >>= 1) { if (t < s) red[t] = fmaxf(red[t], red[t+s]); __syncthreads(); }
    mx = red[0]; __syncthreads();
    float* dst = g_ksm + (size_t)bk*NTOK;
    float sum = 0.f;
    for (int m = t; m < NTOK; m += 256) {
        float e = expf(g_k[base + (size_t)m*16] - mx);
        dst[m] = e; sum += e;
    }
    red[t] = sum; __syncthreads();
    for (int s = 128; s > 0; s >>= 1) { if (t < s) red[t] += red[t+s]; __syncthreads(); }
    float inv = 1.0f / red[0];
    for (int m = t; m < NTOK; m += 256) dst[m] *= inv;
}

// ---------------- K3b: BN(V) -> fp32 [m][col] + bf16 hi/lo [col][m] -------
__global__ void k_vt() {
    __shared__ unsigned short hi[256][36], lo[256][36];
    int t = threadIdx.x;
    int m0 = blockIdx.x * 32;           // 72 blocks
    int b = t >> 5, v = t & 31;
    float sc = g_vaff[v], sh = g_vaff[32+v];
    #pragma unroll 4
    for (int i = 0; i < 32; i++) {
        int m = m0 + i;
        float xv = g_v[((size_t)b*NTOK + m)*32 + v] * sc + sh;
        g_vt[(size_t)m*256 + t] = xv;
        __nv_bfloat16 h = __float2bfloat16(xv);
        float l = xv - __bfloat162float(h);
        hi[t][i] = __bfloat16_as_ushort(h);
        lo[t][i] = __bfloat16_as_ushort(__float2bfloat16(l));
    }
    __syncthreads();
    uint32_t* dh = (uint32_t*)(g_vthi + (size_t)t*NTOK + m0);
    uint32_t* dl = (uint32_t*)(g_vtlo + (size_t)t*NTOK + m0);
    #pragma unroll
    for (int j = 0; j < 16; j++) {
        dh[j] = ((uint32_t)hi[t][2*j+1] << 16) | hi[t][2*j];
        dl[j] = ((uint32_t)lo[t][2*j+1] << 16) | lo[t][2*j];
    }
}

// ---------------- K4: content lambda lamc ---------------------------------
__global__ void k_lamc_part() {
    __shared__ float Ks[16*128];
    __shared__ float Vs[128*32];
    int b = blockIdx.x / 18, mc = blockIdx.x - b*18;
    int m0 = mc * 128;
    int t = threadIdx.x;
    for (int i = t; i < 2048; i += 512) { int k = i>>7, mm = i&127; Ks[i] = g_ksm[(size_t)(b*16+k)*NTOK + m0+mm]; }
    for (int i = t; i < 4096; i += 512) { int mm = i>>5, v = i&31;  Vs[i] = g_vt[(size_t)(m0+mm)*256 + b*32 + v]; }
    __syncthreads();
    int k = t >> 5, v = t & 31;
    float acc = 0.f;
    #pragma unroll 8
    for (int mm = 0; mm < 128; mm++) acc += Ks[k*128+mm] * Vs[mm*32+v];
    g_lamc_part[(size_t)blockIdx.x*512 + t] = acc;
}
__global__ void k_lamc_red() {
    int b = blockIdx.x, t = threadIdx.x;
    float s = 0.f;
    for (int mc = 0; mc < 18; mc++) s += g_lamc_part[(size_t)(b*18+mc)*512 + t];
    g_lamc[b*512 + t] = s;
}

// ---------------- K5: BIG GEMM via warp HMMA (bf16-split, 3 passes) -------
// C[(n,k), (b,v)] = sum_m emb[n,m,k] * Vt[(b,v), m]
// CTA: M=128 (8 n x 16 k), N=256, K-chunk=64; 512 thr = 16 warps (4M x 4N),
// warp tile 32x64 via mma.m16n8k16 bf16. Double-buffered SMEM.
#define TK    64
#define NCH   (GK/TK)      // 36
#define A_HI  0
#define A_LO  16384
#define B_HI  32768
#define B_LO  65536
#define STG   98304
#define SMEM_MMA (2*STG)   // 196608

__global__ void __launch_bounds__(512, 1) k_lamp_hmma(const float* __restrict__ R) {
    extern __shared__ char smem[];
    uint32_t sb = smem_u32(smem);
    int t = threadIdx.x;
    int nbase = blockIdx.x * 8;

    // A-gather role (threads 0-255): 8 n x 32 m-pairs
    int n_loc = (t >> 5) & 7, mi2 = t & 31;
    int n = nbase + n_loc;
    int n_row = n / 48, n_col = n - n_row*48;
    // B-copy role (threads 256-511)
    int tb = t - 256;

    // compute role
    int wid = t >> 5, lane = t & 31;
    int wm = wid >> 2, wn = wid & 3;
    int lr = lane & 15, lc = (lane >> 4) * 16;

    float acc[2][8][4];
    #pragma unroll
    for (int i = 0; i < 2; i++)
        #pragma unroll
        for (int j = 0; j < 8; j++)
            #pragma unroll
            for (int q = 0; q < 4; q++) acc[i][j][q] = 0.f;

    auto load_stage = [&](int c, int p) {
        int m0 = c * TK;
        if (t < 256) {
            char* stg_ = smem + p*STG;
            int ma = m0 + mi2*2, mb2 = ma + 1;
            int mra = ma / 48, mca = ma - mra*48;
            int mrb = mb2 / 48, mcb = mb2 - mrb*48;
            const float4* pa = (const float4*)(R + (((mra - n_row + 47)*95 + (mca - n_col + 47)) << 4));
            const float4* pb = (const float4*)(R + (((mrb - n_row + 47)*95 + (mcb - n_col + 47)) << 4));
            float va[16], vb[16];
            *(float4*)&va[0]  = pa[0]; *(float4*)&va[4]  = pa[1];
            *(float4*)&va[8]  = pa[2]; *(float4*)&va[12] = pa[3];
            *(float4*)&vb[0]  = pb[0]; *(float4*)&vb[4]  = pb[1];
            *(float4*)&vb[8]  = pb[2]; *(float4*)&vb[12] = pb[3];
            #pragma unroll
            for (int k = 0; k < 16; k++) {
                __nv_bfloat16 ha = __float2bfloat16(va[k]);
                __nv_bfloat16 hb = __float2bfloat16(vb[k]);
                uint32_t hw = ((uint32_t)__bfloat16_as_ushort(hb) << 16) | __bfloat16_as_ushort(ha);
                float la = va[k] - __bfloat162float(ha);
                float lb = vb[k] - __bfloat162float(hb);
                uint32_t lw = ((uint32_t)__bfloat16_as_ushort(__float2bfloat16(lb)) << 16)
                            | __bfloat16_as_ushort(__float2bfloat16(la));
                uint32_t row = (uint32_t)(n_loc*16 + k);
                uint32_t off = (row*128u + (uint32_t)mi2*4u) ^ ((row & 7u) << 4);
                *(uint32_t*)(stg_ + A_HI + off) = hw;
                *(uint32_t*)(stg_ + A_LO + off) = lw;
            }
        } else {
            uint32_t sa = sb + p*STG;
            #pragma unroll
            for (int i = 0; i < 8; i++) {
                int idx = tb*8 + i;
                uint32_t row = (uint32_t)(idx >> 3), ch = (uint32_t)(idx & 7);
                uint32_t off = (row*128u + ch*16u) ^ ((row & 7u) << 4);
                const char* gh = (const char*)(g_vthi + (size_t)row*NTOK + m0) + ch*16;
                const char* gl = (const char*)(g_vtlo + (size_t)row*NTOK + m0) + ch*16;
                cp16(sa + B_HI + off, gh);
                cp16(sa + B_LO + off, gl);
            }
        }
    };

    load_stage(0, 0);
    CP_COMMIT();

    for (int c = 0; c < NCH; c++) {
        int p = c & 1;
        if (c + 1 < NCH) {
            load_stage(c + 1, 1 - p);
            CP_COMMIT();
            CP_WAIT1();
        } else {
            CP_WAIT0();
        }
        __syncthreads();

        // ---- compute chunk c from stage p
        uint32_t sa = sb + p*STG;
        #pragma unroll
        for (int kk = 0; kk < 4; kk++) {
            uint32_t kb = (uint32_t)(kk * 32);
            uint32_t ah[8], al[8], bb[16];
            uint32_t baddr[4];
            #pragma unroll
            for (int mf = 0; mf < 2; mf++) {
                uint32_t row = (uint32_t)(wm*32 + mf*16 + lr);
                uint32_t off = (row*128u + kb + (uint32_t)lc) ^ ((row & 7u) << 4);
                ldmx4(ah + mf*4, sa + A_HI + off);
                ldmx4(al + mf*4, sa + A_LO + off);
            }
            #pragma unroll
            for (int ng = 0; ng < 4; ng++) {
                uint32_t row = (uint32_t)(wn*64 + ng*16 + lr);
                uint32_t off = (row*128u + kb + (uint32_t)lc) ^ ((row & 7u) << 4);
                baddr[ng] = sa + B_HI + off;
                ldmx4(bb + ng*4, baddr[ng]);
            }
            #pragma unroll
            for (int mf = 0; mf < 2; mf++)
                #pragma unroll
                for (int nf = 0; nf < 8; nf++)
                    mma16816(acc[mf][nf], ah + mf*4, bb[(nf>>1)*4 + (nf&1)], bb[(nf>>1)*4 + (nf&1) + 2]);
            #pragma unroll
            for (int mf = 0; mf < 2; mf++)
                #pragma unroll
                for (int nf = 0; nf < 8; nf++)
                    mma16816(acc[mf][nf], al + mf*4, bb[(nf>>1)*4 + (nf&1)], bb[(nf>>1)*4 + (nf&1) + 2]);
            #pragma unroll
            for (int ng = 0; ng < 4; ng++)
                ldmx4(bb + ng*4, baddr[ng] + (B_LO - B_HI));
            #pragma unroll
            for (int mf = 0; mf < 2; mf++)
                #pragma unroll
                for (int nf = 0; nf < 8; nf++)
                    mma16816(acc[mf][nf], ah + mf*4, bb[(nf>>1)*4 + (nf&1)], bb[(nf>>1)*4 + (nf&1) + 2]);
        }
        __syncthreads();
    }

    // ---- epilogue: write accumulators
    #pragma unroll
    for (int mf = 0; mf < 2; mf++) {
        #pragma unroll
        for (int nf = 0; nf < 8; nf++) {
            int r0 = blockIdx.x*128 + wm*32 + mf*16 + (lane >> 2);
            int c0 = wn*64 + nf*8 + (lane & 3)*2;
            *(float2*)&g_lamp[(size_t)r0*256 + c0]     = make_float2(acc[mf][nf][0], acc[mf][nf][1]);
            *(float2*)&g_lamp[(size_t)(r0+8)*256 + c0] = make_float2(acc[mf][nf][2], acc[mf][nf][3]);
        }
    }
}

// ---------------- K6: consumers -> appearance + motion --------------------
__global__ void k_out(const float* __restrict__ cor,
                      const float* __restrict__ Wce, const float* __restrict__ bce,
                      const float* __restrict__ Wcc, const float* __restrict__ Wmp,
                      const float* __restrict__ bmp,
                      float* __restrict__ app, float* __restrict__ mot) {
    extern __shared__ float sm[];
    float* WccT  = sm;
    float* WmpT  = sm + 8320;
    float* WceS  = sm + 16576;
    float* bceS  = sm + 16704;
    float* bmpS  = sm + 16768;
    float* lamcS = sm + 16896;
    float* grp   = sm + 17408;
    int t = threadIdx.x;
    int g = t >> 7, t1 = t & 127;
    int b = (blockIdx.x * 8) / NTOK;

    for (int i = t; i < 8192; i += 256) { int o = i>>7, c = i&127; WccT[c*65 + o]  = Wcc[i]; }
    for (int i = t; i < 8192; i += 256) { int o = i>>6, c = i&63;  WmpT[c*129 + o] = Wmp[i]; }
    if (t < 128) WceS[t] = Wce[t];
    if (t < 64)  bceS[t] = bce[t];
    if (t < 128) bmpS[t] = bmp[t];
    for (int i = t; i < 512; i += 256) lamcS[i] = g_lamc[b*512 + i];
    __syncthreads();

    float* Qn   = grp + g*832;
    float* ceS  = Qn + 64;
    float* Ltot = ceS + 64;
    float* crow = Ltot + 512;
    float* dif  = crow + 128;

    for (int it = 0; it < 4; it++) {
        int row = blockIdx.x*8 + it*2 + g;
        int n = row - b*NTOK;
        for (int i = t1; i < 512; i += 128) {
            int k = i >> 5, v = i & 31;
            Ltot[i] = lamcS[i] + g_lamp[(size_t)(n*16 + k)*256 + b*32 + v];
        }
        if (t1 < 64) {
            Qn[t1] = g_q[(size_t)row*64 + t1] * g_qaff[t1] + g_qaff[64+t1];
        } else {
            int o = t1 - 64;
            float c0 = cor[(size_t)row*2], c1 = cor[(size_t)row*2 + 1];
            ceS[o] = c0*WceS[o*2] + c1*WceS[o*2+1] + bceS[o];
        }
        __syncthreads();
        {
            int h = t1 >> 5, v = t1 & 31;
            float y = 0.f, cr = 0.f;
            #pragma unroll
            for (int k = 0; k < 16; k++) {
                float a = Ltot[k*32 + v];
                y  += Qn[h*16 + k]  * a;
                cr += ceS[h*16 + k] * a;
            }
            app[(size_t)row*128 + t1] = y;
            crow[t1] = cr;
        }
        __syncthreads();
        if (t1 < 64) {
            float s = 0.f;
            #pragma unroll 4
            for (int c = 0; c < 128; c++) s += crow[c] * WccT[c*65 + t1];
            dif[t1] = s - ceS[t1];
        }
        __syncthreads();
        {
            float s = bmpS[t1];
            #pragma unroll 4
            for (int c = 0; c < 64; c++) s += dif[c] * WmpT[c*129 + t1];
            mot[(size_t)row*128 + t1] = s;
        }
        __syncthreads();
    }
}

// ---------------- launch ---------------------------------------------------
extern "C" void kernel_launch(void* const* d_in, const int* in_sizes, int n_in,
                              void* d_out, int out_size) {
    const float* x   = (const float*)d_in[0];
    const float* cor = (const float*)d_in[1];
    const float* Wq  = (const float*)d_in[2];
    const float* Wk  = (const float*)d_in[3];
    const float* Wv  = (const float*)d_in[4];
    const float* Wce = (const float*)d_in[5];
    const float* bce = (const float*)d_in[6];
    const float* Wcc = (const float*)d_in[7];
    const float* Wmp = (const float*)d_in[8];
    const float* bmp = (const float*)d_in[9];
    const float* gq  = (const float*)d_in[10];
    const float* bq  = (const float*)d_in[11];
    const float* gv  = (const float*)d_in[12];
    const float* bv  = (const float*)d_in[13];
    const float* rpe = (const float*)d_in[14];
    float* app = (float*)d_out;
    float* mot = app + (size_t)NROW*128;

    cudaFuncSetAttribute(k_proj, cudaFuncAttributeMaxDynamicSharedMemorySize, (128*113 + 512)*4);
    cudaFuncSetAttribute(k_out,  cudaFuncAttributeMaxDynamicSharedMemorySize, 19072*4);
    cudaFuncSetAttribute(k_lamp_hmma, cudaFuncAttributeMaxDynamicSharedMemorySize, SMEM_MMA);

    k_proj<<<NROW/16, 128, (128*113 + 512)*4>>>(x, Wq, Wk, Wv);
    k_stats<<<96, 256>>>(gq, bq, gv, bv);
    k_softmax<<<128, 256>>>();
    k_vt<<<72, 256>>>();
    k_lamc_part<<<144, 512>>>();
    k_lamc_red<<<8, 512>>>();
    k_lamp_hmma<<<288, 512, SMEM_MMA>>>(rpe);
    k_out<<<NROW/8, 256, 19072*4>>>(cor, Wce, bce, Wcc, Wmp, bmp, app, mot);
}

// round 5
// speedup vs baseline: 1.5322x; 1.0035x over previous
#include <cuda_runtime.h>
#include <cuda_bf16.h>
#include <math.h>
#include <stdint.h>

#define B_    8
#define NTOK  2304
#define NROW  (B_*NTOK)      // 18432
#define HK    64
#define KD    16
#define VD    32
#define GM    (NTOK*KD)      // 36864
#define GN    (B_*VD)        // 256
#define GK    NTOK           // 2304

// ---------------- scratch (device globals; no allocations) ----------------
__device__ __align__(256) float g_q[(size_t)NROW*HK];
__device__ __align__(256) float g_k[(size_t)NROW*KD];
__device__ __align__(256) float g_v[(size_t)NROW*VD];
__device__ __align__(256) float g_ksm[(size_t)B_*KD*NTOK];
__device__ __align__(256) float g_vt[(size_t)NTOK*GN];                 // BN(V) [m][(b,v)] fp32
__device__ __align__(256) __nv_bfloat16 g_vthi[(size_t)GN*NTOK];       // [(b,v)][m] bf16 hi
__device__ __align__(256) __nv_bfloat16 g_vtlo[(size_t)GN*NTOK];       // [(b,v)][m] bf16 lo
__device__ __align__(256) float g_lamc_part[(size_t)144*KD*VD];
__device__ __align__(256) float g_lamc[(size_t)B_*KD*VD];
__device__ __align__(256) float g_qaff[2*HK];
__device__ __align__(256) float g_vaff[2*VD];
__device__ __align__(256) float g_lamp[(size_t)GM*GN];

// ---------------- portable PTX helpers (no 'a'-features) -------------------
__device__ __forceinline__ uint32_t smem_u32(const void* p) {
    uint32_t a;
    asm("{ .reg .u64 t; cvta.to.shared.u64 t, %1; cvt.u32.u64 %0, t; }" : "=r"(a) : "l"(p));
    return a;
}
__device__ __forceinline__ void ldmx4(uint32_t* r, uint32_t addr) {
    asm volatile("ldmatrix.sync.aligned.m8n8.x4.shared.b16 {%0,%1,%2,%3}, [%4];"
        : "=r"(r[0]), "=r"(r[1]), "=r"(r[2]), "=r"(r[3]) : "r"(addr));
}
__device__ __forceinline__ void mma16816(float* d, const uint32_t* a, uint32_t b0, uint32_t b1) {
    asm volatile("mma.sync.aligned.m16n8k16.row.col.f32.bf16.bf16.f32 "
        "{%0,%1,%2,%3}, {%4,%5,%6,%7}, {%8,%9}, {%0,%1,%2,%3};"
        : "+f"(d[0]), "+f"(d[1]), "+f"(d[2]), "+f"(d[3])
        : "r"(a[0]), "r"(a[1]), "r"(a[2]), "r"(a[3]), "r"(b0), "r"(b1));
}
__device__ __forceinline__ void cp16(uint32_t saddr, const void* g) {
    asm volatile("cp.async.cg.shared.global [%0], [%1], 16;" :: "r"(saddr), "l"(g));
}
#define CP_COMMIT() asm volatile("cp.async.commit_group;" ::: "memory")
#define CP_WAIT1()  asm volatile("cp.async.wait_group 1;" ::: "memory")
#define CP_WAIT0()  asm volatile("cp.async.wait_group 0;" ::: "memory")

// ---------------- K1: fused q/k/v 1x1 conv (with batch reversal) ----------
__global__ void k_proj(const float* __restrict__ x,
                       const float* __restrict__ Wq,
                       const float* __restrict__ Wk,
                       const float* __restrict__ Wv) {
    extern __shared__ float sm[];
    float* Ws = sm;
    float* xs = sm + 128*113;
    int t = threadIdx.x;
    for (int idx = t; idx < 112*128; idx += 128) {
        int o = idx >> 7, c = idx & 127;
        float w;
        if (o < 64)      w = Wq[o*128 + c];
        else if (o < 80) w = Wk[(o-64)*128 + c];
        else             w = Wv[(o-80)*128 + c];
        Ws[c*113 + o] = w;
    }
    __syncthreads();
    int row0 = blockIdx.x * 16;
    for (int rr = 0; rr < 16; rr += 4) {
        for (int cidx = t; cidx < 512; cidx += 128) {
            int r = cidx >> 7, i = cidx & 127;
            xs[cidx] = x[(size_t)(row0+rr+r)*128 + i];
        }
        __syncthreads();
        if (t < 112) {
            float a0=0.f, a1=0.f, a2=0.f, a3=0.f;
            #pragma unroll 8
            for (int i = 0; i < 128; i++) {
                float w = Ws[i*113 + t];
                a0 += w*xs[i]; a1 += w*xs[128+i]; a2 += w*xs[256+i]; a3 += w*xs[384+i];
            }
            float acc[4] = {a0,a1,a2,a3};
            #pragma unroll
            for (int r2 = 0; r2 < 4; r2++) {
                int row = row0 + rr + r2;
                int bs = row / NTOK, n = row - bs*NTOK;
                if (t < 64) {
                    g_q[(size_t)row*64 + t] = acc[r2];
                } else {
                    int drow = ((bs + 4) & 7)*NTOK + n;
                    if (t < 80) g_k[(size_t)drow*16 + (t-64)] = acc[r2];
                    else        g_v[(size_t)drow*32 + (t-80)] = acc[r2];
                }
            }
        }
        __syncthreads();
    }
}

// ---------------- K2: BN batch stats ---------------------------------------
__global__ void k_stats(const float* __restrict__ gq, const float* __restrict__ bq,
                        const float* __restrict__ gv, const float* __restrict__ bv) {
    __shared__ float s1[256], s2[256];
    int ch = blockIdx.x, t = threadIdx.x;
    float a = 0.f, b2 = 0.f;
    if (ch < 64) {
        for (int r = t; r < NROW; r += 256) { float xv = g_q[(size_t)r*64 + ch]; a += xv; b2 += xv*xv; }
    } else {
        int c = ch - 64;
        for (int r = t; r < NROW; r += 256) { float xv = g_v[(size_t)r*32 + c]; a += xv; b2 += xv*xv; }
    }
    s1[t] = a; s2[t] = b2; __syncthreads();
    for (int s = 128; s > 0; s >>= 1) {
        if (t < s) { s1[t] += s1[t+s]; s2[t] += s2[t+s]; }
        __syncthreads();
    }
    if (t == 0) {
        float mu  = s1[0] / (float)NROW;
        float var = s2[0] / (float)NROW - mu*mu;
        if (ch < 64) {
            float sc = gq[ch] * rsqrtf(var + 1e-5f);
            g_qaff[ch] = sc; g_qaff[64+ch] = bq[ch] - mu*sc;
        } else {
            int c = ch - 64;
            float sc = gv[c] * rsqrtf(var + 1e-5f);
            g_vaff[c] = sc; g_vaff[32+c] = bv[c] - mu*sc;
        }
    }
}

// ---------------- K3: softmax over m per (b, kd) ---------------------------
__global__ void k_softmax() {
    __shared__ float red[256];
    int bk = blockIdx.x;
    int kd = bk & 15, b = bk >> 4;
    int t = threadIdx.x;
    size_t base = (size_t)b*NTOK*16 + kd;
    float mx = -1e30f;
    for (int m = t; m < NTOK; m += 256) mx = fmaxf(mx, g_k[base + (size_t)m*16]);
    red[t] = mx; __syncthreads();
    for (int s = 128; s > 0; s >>= 1) { if (t < s) red[t] = fmaxf(red[t], red[t+s]); __syncthreads(); }
    mx = red[0]; __syncthreads();
    float* dst = g_ksm + (size_t)bk*NTOK;
    float sum = 0.f;
    for (int m = t; m < NTOK; m += 256) {
        float e = expf(g_k[base + (size_t)m*16] - mx);
        dst[m] = e; sum += e;
    }
    red[t] = sum; __syncthreads();
    for (int s = 128; s > 0; s >>= 1) { if (t < s) red[t] += red[t+s]; __syncthreads(); }
    float inv = 1.0f / red[0];
    for (int m = t; m < NTOK; m += 256) dst[m] *= inv;
}

// ---------------- K3b: BN(V) -> fp32 [m][col] + bf16 hi/lo [col][m] -------
__global__ void k_vt() {
    __shared__ unsigned short hi[256][36], lo[256][36];
    int t = threadIdx.x;
    int m0 = blockIdx.x * 32;           // 72 blocks
    int b = t >> 5, v = t & 31;
    float sc = g_vaff[v], sh = g_vaff[32+v];
    #pragma unroll 4
    for (int i = 0; i < 32; i++) {
        int m = m0 + i;
        float xv = g_v[((size_t)b*NTOK + m)*32 + v] * sc + sh;
        g_vt[(size_t)m*256 + t] = xv;
        __nv_bfloat16 h = __float2bfloat16(xv);
        float l = xv - __bfloat162float(h);
        hi[t][i] = __bfloat16_as_ushort(h);
        lo[t][i] = __bfloat16_as_ushort(__float2bfloat16(l));
    }
    __syncthreads();
    uint32_t* dh = (uint32_t*)(g_vthi + (size_t)t*NTOK + m0);
    uint32_t* dl = (uint32_t*)(g_vtlo + (size_t)t*NTOK + m0);
    #pragma unroll
    for (int j = 0; j < 16; j++) {
        dh[j] = ((uint32_t)hi[t][2*j+1] << 16) | hi[t][2*j];
        dl[j] = ((uint32_t)lo[t][2*j+1] << 16) | lo[t][2*j];
    }
}

// ---------------- K4: content lambda lamc ---------------------------------
__global__ void k_lamc_part() {
    __shared__ float Ks[16*128];
    __shared__ float Vs[128*32];
    int b = blockIdx.x / 18, mc = blockIdx.x - b*18;
    int m0 = mc * 128;
    int t = threadIdx.x;
    for (int i = t; i < 2048; i += 512) { int k = i>>7, mm = i&127; Ks[i] = g_ksm[(size_t)(b*16+k)*NTOK + m0+mm]; }
    for (int i = t; i < 4096; i += 512) { int mm = i>>5, v = i&31;  Vs[i] = g_vt[(size_t)(m0+mm)*256 + b*32 + v]; }
    __syncthreads();
    int k = t >> 5, v = t & 31;
    float acc = 0.f;
    #pragma unroll 8
    for (int mm = 0; mm < 128; mm++) acc += Ks[k*128+mm] * Vs[mm*32+v];
    g_lamc_part[(size_t)blockIdx.x*512 + t] = acc;
}
__global__ void k_lamc_red() {
    int b = blockIdx.x, t = threadIdx.x;
    float s = 0.f;
    for (int mc = 0; mc < 18; mc++) s += g_lamc_part[(size_t)(b*18+mc)*512 + t];
    g_lamc[b*512 + t] = s;
}

// ---------------- K5: BIG GEMM via warp HMMA (bf16-split, 3 passes) -------
// C[(n,k), (b,v)] = sum_m emb[n,m,k] * Vt[(b,v), m]
// CTA: M=128 (8 n x 16 k), N=256, K-chunk=64; 512 thr = 16 warps (4M x 4N),
// warp tile 32x64 via mma.m16n8k16 bf16. Double-buffered SMEM.
#define TK    64
#define NCH   (GK/TK)      // 36
#define A_HI  0
#define A_LO  16384
#define B_HI  32768
#define B_LO  65536
#define STG   98304
#define SMEM_MMA (2*STG)   // 196608

__global__ void __launch_bounds__(512, 1) k_lamp_hmma(const float* __restrict__ R) {
    extern __shared__ char smem[];
    uint32_t sb = smem_u32(smem);
    int t = threadIdx.x;
    int nbase = blockIdx.x * 8;

    // A-gather role (threads 0-255): 8 n x 32 m-pairs
    int n_loc = (t >> 5) & 7, mi2 = t & 31;
    int n = nbase + n_loc;
    int n_row = n / 48, n_col = n - n_row*48;
    // B-copy role (threads 256-511)
    int tb = t - 256;

    // compute role
    int wid = t >> 5, lane = t & 31;
    int wm = wid >> 2, wn = wid & 3;
    int lr = lane & 15, lc = (lane >> 4) * 16;

    float acc[2][8][4];
    #pragma unroll
    for (int i = 0; i < 2; i++)
        #pragma unroll
        for (int j = 0; j < 8; j++)
            #pragma unroll
            for (int q = 0; q < 4; q++) acc[i][j][q] = 0.f;

    auto load_stage = [&](int c, int p) {
        int m0 = c * TK;
        if (t < 256) {
            char* stg_ = smem + p*STG;
            int ma = m0 + mi2*2, mb2 = ma + 1;
            int mra = ma / 48, mca = ma - mra*48;
            int mrb = mb2 / 48, mcb = mb2 - mrb*48;
            const float4* pa = (const float4*)(R + (((mra - n_row + 47)*95 + (mca - n_col + 47)) << 4));
            const float4* pb = (const float4*)(R + (((mrb - n_row + 47)*95 + (mcb - n_col + 47)) << 4));
            float va[16], vb[16];
            *(float4*)&va[0]  = pa[0]; *(float4*)&va[4]  = pa[1];
            *(float4*)&va[8]  = pa[2]; *(float4*)&va[12] = pa[3];
            *(float4*)&vb[0]  = pb[0]; *(float4*)&vb[4]  = pb[1];
            *(float4*)&vb[8]  = pb[2]; *(float4*)&vb[12] = pb[3];
            #pragma unroll
            for (int k = 0; k < 16; k++) {
                __nv_bfloat16 ha = __float2bfloat16(va[k]);
                __nv_bfloat16 hb = __float2bfloat16(vb[k]);
                uint32_t hw = ((uint32_t)__bfloat16_as_ushort(hb) << 16) | __bfloat16_as_ushort(ha);
                float la = va[k] - __bfloat162float(ha);
                float lb = vb[k] - __bfloat162float(hb);
                uint32_t lw = ((uint32_t)__bfloat16_as_ushort(__float2bfloat16(lb)) << 16)
                            | __bfloat16_as_ushort(__float2bfloat16(la));
                uint32_t row = (uint32_t)(n_loc*16 + k);
                uint32_t off = (row*128u + (uint32_t)mi2*4u) ^ ((row & 7u) << 4);
                *(uint32_t*)(stg_ + A_HI + off) = hw;
                *(uint32_t*)(stg_ + A_LO + off) = lw;
            }
        } else {
            uint32_t sa = sb + p*STG;
            #pragma unroll
            for (int i = 0; i < 8; i++) {
                int idx = tb*8 + i;
                uint32_t row = (uint32_t)(idx >> 3), ch = (uint32_t)(idx & 7);
                uint32_t off = (row*128u + ch*16u) ^ ((row & 7u) << 4);
                const char* gh = (const char*)(g_vthi + (size_t)row*NTOK + m0) + ch*16;
                const char* gl = (const char*)(g_vtlo + (size_t)row*NTOK + m0) + ch*16;
                cp16(sa + B_HI + off, gh);
                cp16(sa + B_LO + off, gl);
            }
        }
    };

    load_stage(0, 0);
    CP_COMMIT();

    for (int c = 0; c < NCH; c++) {
        int p = c & 1;
        if (c + 1 < NCH) {
            load_stage(c + 1, 1 - p);
            CP_COMMIT();
            CP_WAIT1();
        } else {
            CP_WAIT0();
        }
        __syncthreads();

        // ---- compute chunk c from stage p
        uint32_t sa = sb + p*STG;
        #pragma unroll
        for (int kk = 0; kk < 4; kk++) {
            uint32_t kb = (uint32_t)(kk * 32);
            uint32_t ah[8], al[8], bb[16];
            uint32_t baddr[4];
            #pragma unroll
            for (int mf = 0; mf < 2; mf++) {
                uint32_t row = (uint32_t)(wm*32 + mf*16 + lr);
                uint32_t off = (row*128u + kb + (uint32_t)lc) ^ ((row & 7u) << 4);
                ldmx4(ah + mf*4, sa + A_HI + off);
                ldmx4(al + mf*4, sa + A_LO + off);
            }
            #pragma unroll
            for (int ng = 0; ng < 4; ng++) {
                uint32_t row = (uint32_t)(wn*64 + ng*16 + lr);
                uint32_t off = (row*128u + kb + (uint32_t)lc) ^ ((row & 7u) << 4);
                baddr[ng] = sa + B_HI + off;
                ldmx4(bb + ng*4, baddr[ng]);
            }
            #pragma unroll
            for (int mf = 0; mf < 2; mf++)
                #pragma unroll
                for (int nf = 0; nf < 8; nf++)
                    mma16816(acc[mf][nf], ah + mf*4, bb[(nf>>1)*4 + (nf&1)], bb[(nf>>1)*4 + (nf&1) + 2]);
            #pragma unroll
            for (int mf = 0; mf < 2; mf++)
                #pragma unroll
                for (int nf = 0; nf < 8; nf++)
                    mma16816(acc[mf][nf], al + mf*4, bb[(nf>>1)*4 + (nf&1)], bb[(nf>>1)*4 + (nf&1) + 2]);
            #pragma unroll
            for (int ng = 0; ng < 4; ng++)
                ldmx4(bb + ng*4, baddr[ng] + (B_LO - B_HI));
            #pragma unroll
            for (int mf = 0; mf < 2; mf++)
                #pragma unroll
                for (int nf = 0; nf < 8; nf++)
                    mma16816(acc[mf][nf], ah + mf*4, bb[(nf>>1)*4 + (nf&1)], bb[(nf>>1)*4 + (nf&1) + 2]);
        }
        __syncthreads();
    }

    // ---- epilogue: write accumulators
    #pragma unroll
    for (int mf = 0; mf < 2; mf++) {
        #pragma unroll
        for (int nf = 0; nf < 8; nf++) {
            int r0 = blockIdx.x*128 + wm*32 + mf*16 + (lane >> 2);
            int c0 = wn*64 + nf*8 + (lane & 3)*2;
            *(float2*)&g_lamp[(size_t)r0*256 + c0]     = make_float2(acc[mf][nf][0], acc[mf][nf][1]);
            *(float2*)&g_lamp[(size_t)(r0+8)*256 + c0] = make_float2(acc[mf][nf][2], acc[mf][nf][3]);
        }
    }
}

// ---------------- K6: consumers -> appearance + motion --------------------
__global__ void k_out(const float* __restrict__ cor,
                      const float* __restrict__ Wce, const float* __restrict__ bce,
                      const float* __restrict__ Wcc, const float* __restrict__ Wmp,
                      const float* __restrict__ bmp,
                      float* __restrict__ app, float* __restrict__ mot) {
    extern __shared__ float sm[];
    float* WccT  = sm;
    float* WmpT  = sm + 8320;
    float* WceS  = sm + 16576;
    float* bceS  = sm + 16704;
    float* bmpS  = sm + 16768;
    float* lamcS = sm + 16896;
    float* grp   = sm + 17408;
    int t = threadIdx.x;
    int g = t >> 7, t1 = t & 127;
    int b = (blockIdx.x * 8) / NTOK;

    for (int i = t; i < 8192; i += 256) { int o = i>>7, c = i&127; WccT[c*65 + o]  = Wcc[i]; }
    for (int i = t; i < 8192; i += 256) { int o = i>>6, c = i&63;  WmpT[c*129 + o] = Wmp[i]; }
    if (t < 128) WceS[t] = Wce[t];
    if (t < 64)  bceS[t] = bce[t];
    if (t < 128) bmpS[t] = bmp[t];
    for (int i = t; i < 512; i += 256) lamcS[i] = g_lamc[b*512 + i];
    __syncthreads();

    float* Qn   = grp + g*832;
    float* ceS  = Qn + 64;
    float* Ltot = ceS + 64;
    float* crow = Ltot + 512;
    float* dif  = crow + 128;

    for (int it = 0; it < 4; it++) {
        int row = blockIdx.x*8 + it*2 + g;
        int n = row - b*NTOK;
        for (int i = t1; i < 512; i += 128) {
            int k = i >> 5, v = i & 31;
            Ltot[i] = lamcS[i] + g_lamp[(size_t)(n*16 + k)*256 + b*32 + v];
        }
        if (t1 < 64) {
            Qn[t1] = g_q[(size_t)row*64 + t1] * g_qaff[t1] + g_qaff[64+t1];
        } else {
            int o = t1 - 64;
            float c0 = cor[(size_t)row*2], c1 = cor[(size_t)row*2 + 1];
            ceS[o] = c0*WceS[o*2] + c1*WceS[o*2+1] + bceS[o];
        }
        __syncthreads();
        {
            int h = t1 >> 5, v = t1 & 31;
            float y = 0.f, cr = 0.f;
            #pragma unroll
            for (int k = 0; k < 16; k++) {
                float a = Ltot[k*32 + v];
                y  += Qn[h*16 + k]  * a;
                cr += ceS[h*16 + k] * a;
            }
            app[(size_t)row*128 + t1] = y;
            crow[t1] = cr;
        }
        __syncthreads();
        if (t1 < 64) {
            float s = 0.f;
            #pragma unroll 4
            for (int c = 0; c < 128; c++) s += crow[c] * WccT[c*65 + t1];
            dif[t1] = s - ceS[t1];
        }
        __syncthreads();
        {
            float s = bmpS[t1];
            #pragma unroll 4
            for (int c = 0; c < 64; c++) s += dif[c] * WmpT[c*129 + t1];
            mot[(size_t)row*128 + t1] = s;
        }
        __syncthreads();
    }
}

// ---------------- launch ---------------------------------------------------
extern "C" void kernel_launch(void* const* d_in, const int* in_sizes, int n_in,
                              void* d_out, int out_size) {
    const float* x   = (const float*)d_in[0];
    const float* cor = (const float*)d_in[1];
    const float* Wq  = (const float*)d_in[2];
    const float* Wk  = (const float*)d_in[3];
    const float* Wv  = (const float*)d_in[4];
    const float* Wce = (const float*)d_in[5];
    const float* bce = (const float*)d_in[6];
    const float* Wcc = (const float*)d_in[7];
    const float* Wmp = (const float*)d_in[8];
    const float* bmp = (const float*)d_in[9];
    const float* gq  = (const float*)d_in[10];
    const float* bq  = (const float*)d_in[11];
    const float* gv  = (const float*)d_in[12];
    const float* bv  = (const float*)d_in[13];
    const float* rpe = (const float*)d_in[14];
    float* app = (float*)d_out;
    float* mot = app + (size_t)NROW*128;

    cudaFuncSetAttribute(k_proj, cudaFuncAttributeMaxDynamicSharedMemorySize, (128*113 + 512)*4);
    cudaFuncSetAttribute(k_out,  cudaFuncAttributeMaxDynamicSharedMemorySize, 19072*4);
    cudaFuncSetAttribute(k_lamp_hmma, cudaFuncAttributeMaxDynamicSharedMemorySize, SMEM_MMA);

    k_proj<<<NROW/16, 128, (128*113 + 512)*4>>>(x, Wq, Wk, Wv);
    k_stats<<<96, 256>>>(gq, bq, gv, bv);
    k_softmax<<<128, 256>>>();
    k_vt<<<72, 256>>>();
    k_lamc_part<<<144, 512>>>();
    k_lamc_red<<<8, 512>>>();
    k_lamp_hmma<<<288, 512, SMEM_MMA>>>(rpe);
    k_out<<<NROW/8, 256, 19072*4>>>(cor, Wce, bce, Wcc, Wmp, bmp, app, mot);
}

// round 6
// speedup vs baseline: 1.8639x; 1.2164x over previous
#include <cuda_runtime.h>
#include <cuda_bf16.h>
#include <math.h>
#include <stdint.h>

#define B_    8
#define NTOK  2304
#define NROW  (B_*NTOK)      // 18432
#define HK    64
#define KD    16
#define VD    32
#define GM    (NTOK*KD)      // 36864
#define GN    (B_*VD)        // 256
#define GK    NTOK           // 2304
#define RTAB  (95*95*16)     // 144400

// ---------------- scratch (device globals; no allocations) ----------------
__device__ __align__(256) float g_q[(size_t)NROW*HK];
__device__ __align__(256) float g_kT[(size_t)B_*KD*NTOK];              // k transposed [b*16+kd][m]
__device__ __align__(256) float g_v[(size_t)NROW*VD];
__device__ __align__(256) float g_ksm[(size_t)B_*KD*NTOK];
__device__ __align__(256) float g_vt[(size_t)NTOK*GN];                 // BN(V) [m][(b,v)] fp32
__device__ __align__(256) unsigned short g_vthi[(size_t)GN*NTOK];      // [(b,v)][m] bf16 hi
__device__ __align__(256) unsigned short g_vtlo[(size_t)GN*NTOK];      // [(b,v)][m] bf16 lo
__device__ __align__(256) unsigned short g_Rhi[RTAB];                  // rel-pos table bf16 hi
__device__ __align__(256) unsigned short g_Rlo[RTAB];                  // rel-pos table bf16 lo
__device__ __align__(256) float g_part[288*224];                       // BN partials
__device__ __align__(256) float g_lamc_part[(size_t)144*KD*VD];
__device__ __align__(256) float g_lamc[(size_t)B_*KD*VD];
__device__ __align__(256) float g_qaff[2*HK];
__device__ __align__(256) float g_vaff[2*VD];
__device__ __align__(256) float g_lamp[(size_t)GM*GN];

// ---------------- portable PTX helpers (no 'a'-features) -------------------
__device__ __forceinline__ uint32_t smem_u32(const void* p) {
    uint32_t a;
    asm("{ .reg .u64 t; cvta.to.shared.u64 t, %1; cvt.u32.u64 %0, t; }" : "=r"(a) : "l"(p));
    return a;
}
__device__ __forceinline__ void ldmx4(uint32_t* r, uint32_t addr) {
    asm volatile("ldmatrix.sync.aligned.m8n8.x4.shared.b16 {%0,%1,%2,%3}, [%4];"
        : "=r"(r[0]), "=r"(r[1]), "=r"(r[2]), "=r"(r[3]) : "r"(addr));
}
__device__ __forceinline__ void mma16816(float* d, const uint32_t* a, uint32_t b0, uint32_t b1) {
    asm volatile("mma.sync.aligned.m16n8k16.row.col.f32.bf16.bf16.f32 "
        "{%0,%1,%2,%3}, {%4,%5,%6,%7}, {%8,%9}, {%0,%1,%2,%3};"
        : "+f"(d[0]), "+f"(d[1]), "+f"(d[2]), "+f"(d[3])
        : "r"(a[0]), "r"(a[1]), "r"(a[2]), "r"(a[3]), "r"(b0), "r"(b1));
}
__device__ __forceinline__ void cp16(uint32_t saddr, const void* g) {
    asm volatile("cp.async.cg.shared.global [%0], [%1], 16;" :: "r"(saddr), "l"(g));
}
#define CP_COMMIT() asm volatile("cp.async.commit_group;" ::: "memory")
#define CP_WAIT1()  asm volatile("cp.async.wait_group 1;" ::: "memory")
#define CP_WAIT0()  asm volatile("cp.async.wait_group 0;" ::: "memory")

// ---------------- K0: split rel-pos table into bf16 hi/lo ------------------
__global__ void k_splitR(const float* __restrict__ R) {
    int i = blockIdx.x*256 + threadIdx.x;
    if (i < RTAB) {
        float f = R[i];
        __nv_bfloat16 h = __float2bfloat16(f);
        g_Rhi[i] = __bfloat16_as_ushort(h);
        g_Rlo[i] = __bfloat16_as_ushort(__float2bfloat16(f - __bfloat162float(h)));
    }
}

// ---------------- K1: tiled q/k/v 1x1 conv + BN partials -------------------
// C[18432 x 112] = X[18432 x 128] * W^T.  288 blocks x 256 thr, 64x112 tile.
__global__ void __launch_bounds__(256) k_proj(const float* __restrict__ x,
                       const float* __restrict__ Wq,
                       const float* __restrict__ Wk,
                       const float* __restrict__ Wv) {
    __shared__ float Xs[64*33];
    __shared__ float Ws2[112*33];
    __shared__ float red[16*112];
    int t = threadIdx.x;
    int ty = t >> 4, tx = t & 15;
    int row0 = blockIdx.x * 64;
    int bs = blockIdx.x / 36;          // 36 blocks per batch (no straddle)
    float acc[4][7];
    #pragma unroll
    for (int i = 0; i < 4; i++)
        #pragma unroll
        for (int j = 0; j < 7; j++) acc[i][j] = 0.f;

    for (int k0 = 0; k0 < 128; k0 += 32) {
        for (int e = t; e < 2048; e += 256) {
            int r = e >> 5, k = e & 31;
            Xs[r*33 + k] = x[(size_t)(row0+r)*128 + k0 + k];
        }
        for (int e = t; e < 3584; e += 256) {
            int o = e >> 5, k = e & 31;
            float w;
            if (o < 64)      w = Wq[o*128 + k0 + k];
            else if (o < 80) w = Wk[(o-64)*128 + k0 + k];
            else             w = Wv[(o-80)*128 + k0 + k];
            Ws2[o*33 + k] = w;
        }
        __syncthreads();
        #pragma unroll 8
        for (int kk = 0; kk < 32; kk++) {
            float a[4], b[7];
            #pragma unroll
            for (int i = 0; i < 4; i++) a[i] = Xs[(ty*4+i)*33 + kk];
            #pragma unroll
            for (int j = 0; j < 7; j++) b[j] = Ws2[(tx*7+j)*33 + kk];
            #pragma unroll
            for (int i = 0; i < 4; i++)
                #pragma unroll
                for (int j = 0; j < 7; j++) acc[i][j] += a[i]*b[j];
        }
        __syncthreads();
    }

    // outputs
    int db = (bs + 4) & 7;             // frame reversal
    #pragma unroll
    for (int i = 0; i < 4; i++) {
        int row = row0 + ty*4 + i;
        int n = row - bs*NTOK;
        #pragma unroll
        for (int j = 0; j < 7; j++) {
            int o = tx*7 + j;
            float val = acc[i][j];
            if (o < 64)       g_q[(size_t)row*64 + o] = val;
            else if (o < 80)  g_kT[(size_t)(db*16 + o-64)*NTOK + n] = val;
            else              g_v[((size_t)db*NTOK + n)*32 + (o-80)] = val;
        }
    }
    // BN partials (sum, sumsq) for all 112 cols (only q + v used downstream)
    float ps[7], pq[7];
    #pragma unroll
    for (int j = 0; j < 7; j++) {
        ps[j] = acc[0][j]+acc[1][j]+acc[2][j]+acc[3][j];
        pq[j] = acc[0][j]*acc[0][j]+acc[1][j]*acc[1][j]+acc[2][j]*acc[2][j]+acc[3][j]*acc[3][j];
    }
    #pragma unroll
    for (int j = 0; j < 7; j++) red[ty*112 + tx*7 + j] = ps[j];
    __syncthreads();
    if (t < 112) {
        float s = 0.f;
        #pragma unroll
        for (int yy = 0; yy < 16; yy++) s += red[yy*112 + t];
        g_part[blockIdx.x*224 + t] = s;
    }
    __syncthreads();
    #pragma unroll
    for (int j = 0; j < 7; j++) red[ty*112 + tx*7 + j] = pq[j];
    __syncthreads();
    if (t < 112) {
        float s = 0.f;
        #pragma unroll
        for (int yy = 0; yy < 16; yy++) s += red[yy*112 + t];
        g_part[blockIdx.x*224 + 112 + t] = s;
    }
}

// ---------------- K2: reduce BN partials -> affine -------------------------
__global__ void k_affine(const float* __restrict__ gq, const float* __restrict__ bq,
                         const float* __restrict__ gv, const float* __restrict__ bv) {
    int t = threadIdx.x;
    if (t >= 112 || (t >= 64 && t < 80)) return;
    float s = 0.f, s2 = 0.f;
    for (int i = 0; i < 288; i++) {
        s  += g_part[i*224 + t];
        s2 += g_part[i*224 + 112 + t];
    }
    float mu  = s / (float)NROW;
    float var = s2 / (float)NROW - mu*mu;
    if (t < 64) {
        float sc = gq[t] * rsqrtf(var + 1e-5f);
        g_qaff[t] = sc; g_qaff[64+t] = bq[t] - mu*sc;
    } else {
        int c = t - 80;
        float sc = gv[c] * rsqrtf(var + 1e-5f);
        g_vaff[c] = sc; g_vaff[32+c] = bv[c] - mu*sc;
    }
}

// ---------------- K3: softmax over m (coalesced, register-resident) --------
__global__ void k_softmax() {
    __shared__ float red[256];
    int bk = blockIdx.x, t = threadIdx.x;
    const float* src = g_kT + (size_t)bk*NTOK;
    float r[9];
    #pragma unroll
    for (int i = 0; i < 9; i++) r[i] = src[t + i*256];
    float mx = r[0];
    #pragma unroll
    for (int i = 1; i < 9; i++) mx = fmaxf(mx, r[i]);
    red[t] = mx; __syncthreads();
    for (int s = 128; s > 0; s >>= 1) { if (t < s) red[t] = fmaxf(red[t], red[t+s]); __syncthreads(); }
    mx = red[0]; __syncthreads();
    float sum = 0.f;
    #pragma unroll
    for (int i = 0; i < 9; i++) { r[i] = expf(r[i] - mx); sum += r[i]; }
    red[t] = sum; __syncthreads();
    for (int s = 128; s > 0; s >>= 1) { if (t < s) red[t] += red[t+s]; __syncthreads(); }
    float inv = 1.0f / red[0];
    float* dst = g_ksm + (size_t)bk*NTOK;
    #pragma unroll
    for (int i = 0; i < 9; i++) dst[t + i*256] = r[i] * inv;
}

// ---------------- K3b: BN(V) -> fp32 [m][col] + bf16 hi/lo [col][m] -------
__global__ void k_vt() {
    __shared__ unsigned short shi[64][33], slo[64][33];
    int t = threadIdx.x;
    int cg = blockIdx.x & 3, mg = blockIdx.x >> 2;   // 4 x 72
    int col0 = cg*64, m0 = mg*32;
    for (int e = t; e < 2048; e += 256) {
        int lm = e >> 6, lc = e & 63;
        int col = col0 + lc;
        int b = col >> 5, v = col & 31;
        int m = m0 + lm;
        float xv = g_v[((size_t)b*NTOK + m)*32 + v] * g_vaff[v] + g_vaff[32+v];
        g_vt[(size_t)m*256 + col] = xv;
        __nv_bfloat16 h = __float2bfloat16(xv);
        shi[lc][lm] = __bfloat16_as_ushort(h);
        slo[lc][lm] = __bfloat16_as_ushort(__float2bfloat16(xv - __bfloat162float(h)));
    }
    __syncthreads();
    int lc = t >> 2, sub = t & 3;
    uint32_t wh[4], wl[4];
    #pragma unroll
    for (int j = 0; j < 4; j++) {
        wh[j] = (uint32_t)shi[lc][sub*8 + 2*j] | ((uint32_t)shi[lc][sub*8 + 2*j+1] << 16);
        wl[j] = (uint32_t)slo[lc][sub*8 + 2*j] | ((uint32_t)slo[lc][sub*8 + 2*j+1] << 16);
    }
    size_t off = (size_t)(col0 + lc)*NTOK + m0 + sub*8;
    *(uint4*)(g_vthi + off) = make_uint4(wh[0], wh[1], wh[2], wh[3]);
    *(uint4*)(g_vtlo + off) = make_uint4(wl[0], wl[1], wl[2], wl[3]);
}

// ---------------- K4: content lambda lamc ---------------------------------
__global__ void k_lamc_part() {
    __shared__ float Ks[16*128];
    __shared__ float Vs[128*32];
    int b = blockIdx.x / 18, mc = blockIdx.x - b*18;
    int m0 = mc * 128;
    int t = threadIdx.x;
    for (int i = t; i < 2048; i += 512) { int k = i>>7, mm = i&127; Ks[i] = g_ksm[(size_t)(b*16+k)*NTOK + m0+mm]; }
    for (int i = t; i < 4096; i += 512) { int mm = i>>5, v = i&31;  Vs[i] = g_vt[(size_t)(m0+mm)*256 + b*32 + v]; }
    __syncthreads();
    int k = t >> 5, v = t & 31;
    float acc = 0.f;
    #pragma unroll 8
    for (int mm = 0; mm < 128; mm++) acc += Ks[k*128+mm] * Vs[mm*32+v];
    g_lamc_part[(size_t)blockIdx.x*512 + t] = acc;
}
__global__ void k_lamc_red() {
    int b = blockIdx.x, t = threadIdx.x;
    float s = 0.f;
    for (int mc = 0; mc < 18; mc++) s += g_lamc_part[(size_t)(b*18+mc)*512 + t];
    g_lamc[b*512 + t] = s;
}

// ---------------- K5: BIG GEMM via warp HMMA (bf16-split, pipelined) ------
#define TK    64
#define NCH   (GK/TK)      // 36
#define A_HI  0
#define A_LO  16384
#define B_HI  32768
#define B_LO  65536
#define STG   98304
#define SMEM_MMA (2*STG)   // 196608

__global__ void __launch_bounds__(512, 1) k_lamp_hmma() {
    extern __shared__ char smem[];
    uint32_t sb = smem_u32(smem);
    int t = threadIdx.x;
    int nbase = blockIdx.x * 8;

    // A-gather role: all 512 threads, one (n_loc, m) pair each
    int n_loc = t >> 6, mi = t & 63;
    int n = nbase + n_loc;
    int n_row = n / 48, n_col = n - n_row*48;
    bool even = !(t & 1);

    // compute role
    int wid = t >> 5, lane = t & 31;
    int wm = wid >> 2, wn = wid & 3;
    int lr = lane & 15, lc = (lane >> 4) * 16;

    float acc[2][8][4];
    #pragma unroll
    for (int i = 0; i < 2; i++)
        #pragma unroll
        for (int j = 0; j < 8; j++)
            #pragma unroll
            for (int q = 0; q < 4; q++) acc[i][j][q] = 0.f;

    uint4 h0, h1, l0, l1;    // A prefetch registers

    auto ldgA = [&](int c) {
        int m = c*TK + mi;
        int mr = m / 48, mc2 = m - mr*48;
        size_t idx = (size_t)((mr - n_row + 47)*95 + (mc2 - n_col + 47)) * 16;
        const uint4* ph = (const uint4*)(g_Rhi + idx);
        const uint4* pl = (const uint4*)(g_Rlo + idx);
        h0 = ph[0]; h1 = ph[1];
        l0 = pl[0]; l1 = pl[1];
    };
    auto stsA = [&](int p) {
        char* stg_ = smem + p*STG + (even ? A_HI : A_LO);
        uint32_t hw[8] = {h0.x,h0.y,h0.z,h0.w,h1.x,h1.y,h1.z,h1.w};
        uint32_t lw[8] = {l0.x,l0.y,l0.z,l0.w,l1.x,l1.y,l1.z,l1.w};
        uint32_t cb = (uint32_t)(mi & 62) * 2;
        #pragma unroll
        for (int r = 0; r < 8; r++) {
            uint32_t send = even ? lw[r] : hw[r];
            uint32_t got  = __shfl_xor_sync(0xffffffffu, send, 1);
            uint32_t a = even ? hw[r] : got;      // m-even value
            uint32_t b = even ? got   : lw[r];    // m-odd value
            uint32_t w0 = __byte_perm(a, b, 0x5410);
            uint32_t w1 = __byte_perm(a, b, 0x7632);
            uint32_t r0 = (uint32_t)(n_loc*16 + 2*r);
            uint32_t r1 = r0 + 1;
            *(uint32_t*)(stg_ + ((r0*128u + cb) ^ ((r0 & 7u) << 4))) = w0;
            *(uint32_t*)(stg_ + ((r1*128u + cb) ^ ((r1 & 7u) << 4))) = w1;
        }
    };
    auto cpB = [&](int c, int p) {
        int m0 = c * TK;
        uint32_t sa = sb + p*STG;
        const unsigned short* srcT = (t < 256) ? g_vthi : g_vtlo;
        uint32_t rgn = (t < 256) ? B_HI : B_LO;
        int tt = t & 255;
        #pragma unroll
        for (int i = 0; i < 8; i++) {
            int idx = tt*8 + i;
            uint32_t row = (uint32_t)(idx >> 3), ch = (uint32_t)(idx & 7);
            uint32_t off = (row*128u + ch*16u) ^ ((row & 7u) << 4);
            cp16(sa + rgn + off, (const char*)(srcT + (size_t)row*NTOK + m0) + ch*16);
        }
    };

    // prologue
    ldgA(0);
    cpB(0, 0); CP_COMMIT();
    stsA(0);
    ldgA(1);
    cpB(1, 1); CP_COMMIT();
    CP_WAIT1();
    __syncthreads();

    int p = 0;
    for (int c = 0; c < NCH; c++) {
        // ---- compute chunk c from stage p
        uint32_t sa = sb + p*STG;
        #pragma unroll
        for (int kk = 0; kk < 4; kk++) {
            uint32_t kb = (uint32_t)(kk * 32);
            uint32_t ah[8], al[8], bb[16];
            uint32_t baddr[4];
            #pragma unroll
            for (int mf = 0; mf < 2; mf++) {
                uint32_t row = (uint32_t)(wm*32 + mf*16 + lr);
                uint32_t off = (row*128u + kb + (uint32_t)lc) ^ ((row & 7u) << 4);
                ldmx4(ah + mf*4, sa + A_HI + off);
                ldmx4(al + mf*4, sa + A_LO + off);
            }
            #pragma unroll
            for (int ng = 0; ng < 4; ng++) {
                uint32_t row = (uint32_t)(wn*64 + ng*16 + lr);
                uint32_t off = (row*128u + kb + (uint32_t)lc) ^ ((row & 7u) << 4);
                baddr[ng] = sa + B_HI + off;
                ldmx4(bb + ng*4, baddr[ng]);
            }
            #pragma unroll
            for (int mf = 0; mf < 2; mf++)
                #pragma unroll
                for (int nf = 0; nf < 8; nf++)
                    mma16816(acc[mf][nf], ah + mf*4, bb[(nf>>1)*4 + (nf&1)], bb[(nf>>1)*4 + (nf&1) + 2]);
            #pragma unroll
            for (int mf = 0; mf < 2; mf++)
                #pragma unroll
                for (int nf = 0; nf < 8; nf++)
                    mma16816(acc[mf][nf], al + mf*4, bb[(nf>>1)*4 + (nf&1)], bb[(nf>>1)*4 + (nf&1) + 2]);
            #pragma unroll
            for (int ng = 0; ng < 4; ng++)
                ldmx4(bb + ng*4, baddr[ng] + (B_LO - B_HI));
            #pragma unroll
            for (int mf = 0; mf < 2; mf++)
                #pragma unroll
                for (int nf = 0; nf < 8; nf++)
                    mma16816(acc[mf][nf], ah + mf*4, bb[(nf>>1)*4 + (nf&1)], bb[(nf>>1)*4 + (nf&1) + 2]);
        }
        // ---- pipeline: A(c+1) regs -> smem (other buf), prefetch A(c+2)
        if (c + 1 < NCH) stsA(1 - p);
        if (c + 2 < NCH) ldgA(c + 2);
        CP_WAIT0();                 // B(c+1) complete
        __syncthreads();            // buf p free; A(c+1)+B(c+1) visible
        if (c + 2 < NCH) { cpB(c + 2, p); CP_COMMIT(); }
        p ^= 1;
    }

    // ---- epilogue: write accumulators
    #pragma unroll
    for (int mf = 0; mf < 2; mf++) {
        #pragma unroll
        for (int nf = 0; nf < 8; nf++) {
            int r0 = blockIdx.x*128 + wm*32 + mf*16 + (lane >> 2);
            int c0 = wn*64 + nf*8 + (lane & 3)*2;
            *(float2*)&g_lamp[(size_t)r0*256 + c0]     = make_float2(acc[mf][nf][0], acc[mf][nf][1]);
            *(float2*)&g_lamp[(size_t)(r0+8)*256 + c0] = make_float2(acc[mf][nf][2], acc[mf][nf][3]);
        }
    }
}

// ---------------- K6: consumers -> appearance + motion --------------------
__global__ void k_out(const float* __restrict__ cor,
                      const float* __restrict__ Wce, const float* __restrict__ bce,
                      const float* __restrict__ Wcc, const float* __restrict__ Wmp,
                      const float* __restrict__ bmp,
                      float* __restrict__ app, float* __restrict__ mot) {
    extern __shared__ float sm[];
    float* WccT  = sm;
    float* WmpT  = sm + 8320;
    float* WceS  = sm + 16576;
    float* bceS  = sm + 16704;
    float* bmpS  = sm + 16768;
    float* lamcS = sm + 16896;
    float* grp   = sm + 17408;
    int t = threadIdx.x;
    int g = t >> 7, t1 = t & 127;
    int b = (blockIdx.x * 8) / NTOK;

    for (int i = t; i < 8192; i += 256) { int o = i>>7, c = i&127; WccT[c*65 + o]  = Wcc[i]; }
    for (int i = t; i < 8192; i += 256) { int o = i>>6, c = i&63;  WmpT[c*129 + o] = Wmp[i]; }
    if (t < 128) WceS[t] = Wce[t];
    if (t < 64)  bceS[t] = bce[t];
    if (t < 128) bmpS[t] = bmp[t];
    for (int i = t; i < 512; i += 256) lamcS[i] = g_lamc[b*512 + i];
    __syncthreads();

    float* Qn   = grp + g*832;
    float* ceS  = Qn + 64;
    float* Ltot = ceS + 64;
    float* crow = Ltot + 512;
    float* dif  = crow + 128;

    for (int it = 0; it < 4; it++) {
        int row = blockIdx.x*8 + it*2 + g;
        int n = row - b*NTOK;
        for (int i = t1; i < 512; i += 128) {
            int k = i >> 5, v = i & 31;
            Ltot[i] = lamcS[i] + g_lamp[(size_t)(n*16 + k)*256 + b*32 + v];
        }
        if (t1 < 64) {
            Qn[t1] = g_q[(size_t)row*64 + t1] * g_qaff[t1] + g_qaff[64+t1];
        } else {
            int o = t1 - 64;
            float c0 = cor[(size_t)row*2], c1 = cor[(size_t)row*2 + 1];
            ceS[o] = c0*WceS[o*2] + c1*WceS[o*2+1] + bceS[o];
        }
        __syncthreads();
        {
            int h = t1 >> 5, v = t1 & 31;
            float y = 0.f, cr = 0.f;
            #pragma unroll
            for (int k = 0; k < 16; k++) {
                float a = Ltot[k*32 + v];
                y  += Qn[h*16 + k]  * a;
                cr += ceS[h*16 + k] * a;
            }
            app[(size_t)row*128 + t1] = y;
            crow[t1] = cr;
        }
        __syncthreads();
        if (t1 < 64) {
            float s = 0.f;
            #pragma unroll 4
            for (int c = 0; c < 128; c++) s += crow[c] * WccT[c*65 + t1];
            dif[t1] = s - ceS[t1];
        }
        __syncthreads();
        {
            float s = bmpS[t1];
            #pragma unroll 4
            for (int c = 0; c < 64; c++) s += dif[c] * WmpT[c*129 + t1];
            mot[(size_t)row*128 + t1] = s;
        }
        __syncthreads();
    }
}

// ---------------- launch ---------------------------------------------------
extern "C" void kernel_launch(void* const* d_in, const int* in_sizes, int n_in,
                              void* d_out, int out_size) {
    const float* x   = (const float*)d_in[0];
    const float* cor = (const float*)d_in[1];
    const float* Wq  = (const float*)d_in[2];
    const float* Wk  = (const float*)d_in[3];
    const float* Wv  = (const float*)d_in[4];
    const float* Wce = (const float*)d_in[5];
    const float* bce = (const float*)d_in[6];
    const float* Wcc = (const float*)d_in[7];
    const float* Wmp = (const float*)d_in[8];
    const float* bmp = (const float*)d_in[9];
    const float* gq  = (const float*)d_in[10];
    const float* bq  = (const float*)d_in[11];
    const float* gv  = (const float*)d_in[12];
    const float* bv  = (const float*)d_in[13];
    const float* rpe = (const float*)d_in[14];
    float* app = (float*)d_out;
    float* mot = app + (size_t)NROW*128;

    cudaFuncSetAttribute(k_out, cudaFuncAttributeMaxDynamicSharedMemorySize, 19072*4);
    cudaFuncSetAttribute(k_lamp_hmma, cudaFuncAttributeMaxDynamicSharedMemorySize, SMEM_MMA);

    k_splitR<<<(RTAB + 255)/256, 256>>>(rpe);
    k_proj<<<288, 256>>>(x, Wq, Wk, Wv);
    k_affine<<<1, 128>>>(gq, bq, gv, bv);
    k_softmax<<<128, 256>>>();
    k_vt<<<288, 256>>>();
    k_lamc_part<<<144, 512>>>();
    k_lamc_red<<<8, 512>>>();
    k_lamp_hmma<<<288, 512, SMEM_MMA>>>();
    k_out<<<NROW/8, 256, 19072*4>>>(cor, Wce, bce, Wcc, Wmp, bmp, app, mot);
}

// round 7
// speedup vs baseline: 3.2030x; 1.7185x over previous
#include <cuda_runtime.h>
#include <cuda_fp16.h>
#include <math.h>
#include <stdint.h>

#define B_    8
#define NTOK  2304
#define NROW  (B_*NTOK)      // 18432
#define HK    64
#define KD    16
#define VD    32
#define GM    (NTOK*KD)      // 36864
#define GN    (B_*VD)        // 256
#define GK    NTOK           // 2304
#define RTAB  (95*95*16)     // 144400

// ---------------- scratch (device globals; no allocations) ----------------
__device__ __align__(256) float g_q[(size_t)NROW*HK];
__device__ __align__(256) float g_kT[(size_t)B_*KD*NTOK];              // k transposed [b*16+kd][m]
__device__ __align__(256) float g_v[(size_t)NROW*VD];
__device__ __align__(256) float g_ksm[(size_t)B_*KD*NTOK];
__device__ __align__(256) float g_vt[(size_t)NTOK*GN];                 // BN(V) [m][(b,v)] fp32
__device__ __align__(256) unsigned short g_vthf[(size_t)GN*NTOK];      // [(b,v)][m] fp16
__device__ __align__(256) unsigned short g_Rh[RTAB];                   // rel-pos table fp16
__device__ __align__(256) float g_part[288*224];                       // BN partials
__device__ __align__(256) float g_lamc_part[(size_t)144*KD*VD];
__device__ __align__(256) float g_lamc[(size_t)B_*KD*VD];
__device__ __align__(256) float g_qaff[2*HK];
__device__ __align__(256) float g_vaff[2*VD];
__device__ __align__(256) float g_lamp[(size_t)GM*GN];

// ---------------- portable PTX helpers (no 'a'-features) -------------------
__device__ __forceinline__ uint32_t smem_u32(const void* p) {
    uint32_t a;
    asm("{ .reg .u64 t; cvta.to.shared.u64 t, %1; cvt.u32.u64 %0, t; }" : "=r"(a) : "l"(p));
    return a;
}
__device__ __forceinline__ void ldmx4(uint32_t* r, uint32_t addr) {
    asm volatile("ldmatrix.sync.aligned.m8n8.x4.shared.b16 {%0,%1,%2,%3}, [%4];"
        : "=r"(r[0]), "=r"(r[1]), "=r"(r[2]), "=r"(r[3]) : "r"(addr));
}
__device__ __forceinline__ void mma16816(float* d, const uint32_t* a, uint32_t b0, uint32_t b1) {
    asm volatile("mma.sync.aligned.m16n8k16.row.col.f32.f16.f16.f32 "
        "{%0,%1,%2,%3}, {%4,%5,%6,%7}, {%8,%9}, {%0,%1,%2,%3};"
        : "+f"(d[0]), "+f"(d[1]), "+f"(d[2]), "+f"(d[3])
        : "r"(a[0]), "r"(a[1]), "r"(a[2]), "r"(a[3]), "r"(b0), "r"(b1));
}
__device__ __forceinline__ void cp16(uint32_t saddr, const void* g) {
    asm volatile("cp.async.cg.shared.global [%0], [%1], 16;" :: "r"(saddr), "l"(g));
}
#define CP_COMMIT() asm volatile("cp.async.commit_group;" ::: "memory")
#define CP_WAIT1()  asm volatile("cp.async.wait_group 1;" ::: "memory")
#define CP_WAIT0()  asm volatile("cp.async.wait_group 0;" ::: "memory")

// ---------------- K1: tiled q/k/v 1x1 conv + BN partials + R convert ------
// blocks 0..287: GEMM C[18432 x 112]; blocks 288..852: fp16-convert R table.
__global__ void __launch_bounds__(256) k_proj(const float* __restrict__ x,
                       const float* __restrict__ Wq,
                       const float* __restrict__ Wk,
                       const float* __restrict__ Wv,
                       const float* __restrict__ R) {
    if (blockIdx.x >= 288) {
        int i = (blockIdx.x - 288)*256 + threadIdx.x;
        if (i < RTAB) g_Rh[i] = __half_as_ushort(__float2half_rn(R[i]));
        return;
    }
    __shared__ float Xs[64*33];
    __shared__ float Ws2[112*33];
    __shared__ float red[16*112];
    int t = threadIdx.x;
    int ty = t >> 4, tx = t & 15;
    int row0 = blockIdx.x * 64;
    int bs = blockIdx.x / 36;
    float acc[4][7];
    #pragma unroll
    for (int i = 0; i < 4; i++)
        #pragma unroll
        for (int j = 0; j < 7; j++) acc[i][j] = 0.f;

    for (int k0 = 0; k0 < 128; k0 += 32) {
        for (int e = t; e < 2048; e += 256) {
            int r = e >> 5, k = e & 31;
            Xs[r*33 + k] = x[(size_t)(row0+r)*128 + k0 + k];
        }
        for (int e = t; e < 3584; e += 256) {
            int o = e >> 5, k = e & 31;
            float w;
            if (o < 64)      w = Wq[o*128 + k0 + k];
            else if (o < 80) w = Wk[(o-64)*128 + k0 + k];
            else             w = Wv[(o-80)*128 + k0 + k];
            Ws2[o*33 + k] = w;
        }
        __syncthreads();
        #pragma unroll 8
        for (int kk = 0; kk < 32; kk++) {
            float a[4], b[7];
            #pragma unroll
            for (int i = 0; i < 4; i++) a[i] = Xs[(ty*4+i)*33 + kk];
            #pragma unroll
            for (int j = 0; j < 7; j++) b[j] = Ws2[(tx*7+j)*33 + kk];
            #pragma unroll
            for (int i = 0; i < 4; i++)
                #pragma unroll
                for (int j = 0; j < 7; j++) acc[i][j] += a[i]*b[j];
        }
        __syncthreads();
    }

    int db = (bs + 4) & 7;
    #pragma unroll
    for (int i = 0; i < 4; i++) {
        int row = row0 + ty*4 + i;
        int n = row - bs*NTOK;
        #pragma unroll
        for (int j = 0; j < 7; j++) {
            int o = tx*7 + j;
            float val = acc[i][j];
            if (o < 64)       g_q[(size_t)row*64 + o] = val;
            else if (o < 80)  g_kT[(size_t)(db*16 + o-64)*NTOK + n] = val;
            else              g_v[((size_t)db*NTOK + n)*32 + (o-80)] = val;
        }
    }
    float ps[7], pq[7];
    #pragma unroll
    for (int j = 0; j < 7; j++) {
        ps[j] = acc[0][j]+acc[1][j]+acc[2][j]+acc[3][j];
        pq[j] = acc[0][j]*acc[0][j]+acc[1][j]*acc[1][j]+acc[2][j]*acc[2][j]+acc[3][j]*acc[3][j];
    }
    #pragma unroll
    for (int j = 0; j < 7; j++) red[ty*112 + tx*7 + j] = ps[j];
    __syncthreads();
    if (t < 112) {
        float s = 0.f;
        #pragma unroll
        for (int yy = 0; yy < 16; yy++) s += red[yy*112 + t];
        g_part[blockIdx.x*224 + t] = s;
    }
    __syncthreads();
    #pragma unroll
    for (int j = 0; j < 7; j++) red[ty*112 + tx*7 + j] = pq[j];
    __syncthreads();
    if (t < 112) {
        float s = 0.f;
        #pragma unroll
        for (int yy = 0; yy < 16; yy++) s += red[yy*112 + t];
        g_part[blockIdx.x*224 + 112 + t] = s;
    }
}

// ---------------- K2: reduce BN partials -> affine -------------------------
__global__ void k_affine(const float* __restrict__ gq, const float* __restrict__ bq,
                         const float* __restrict__ gv, const float* __restrict__ bv) {
    int t = threadIdx.x;
    if (t >= 112 || (t >= 64 && t < 80)) return;
    float s = 0.f, s2 = 0.f;
    for (int i = 0; i < 288; i++) {
        s  += g_part[i*224 + t];
        s2 += g_part[i*224 + 112 + t];
    }
    float mu  = s / (float)NROW;
    float var = s2 / (float)NROW - mu*mu;
    if (t < 64) {
        float sc = gq[t] * rsqrtf(var + 1e-5f);
        g_qaff[t] = sc; g_qaff[64+t] = bq[t] - mu*sc;
    } else {
        int c = t - 80;
        float sc = gv[c] * rsqrtf(var + 1e-5f);
        g_vaff[c] = sc; g_vaff[32+c] = bv[c] - mu*sc;
    }
}

// ---------------- K3b: BN(V) -> fp32 [m][col] + fp16 [col][m] -------------
__global__ void k_vt() {
    __shared__ unsigned short sh[64][33];
    int t = threadIdx.x;
    int cg = blockIdx.x & 3, mg = blockIdx.x >> 2;   // 4 x 72
    int col0 = cg*64, m0 = mg*32;
    for (int e = t; e < 2048; e += 256) {
        int lm = e >> 6, lc = e & 63;
        int col = col0 + lc;
        int b = col >> 5, v = col & 31;
        int m = m0 + lm;
        float xv = g_v[((size_t)b*NTOK + m)*32 + v] * g_vaff[v] + g_vaff[32+v];
        g_vt[(size_t)m*256 + col] = xv;
        sh[lc][lm] = __half_as_ushort(__float2half_rn(xv));
    }
    __syncthreads();
    int lc = t >> 2, sub = t & 3;
    uint32_t w[4];
    #pragma unroll
    for (int j = 0; j < 4; j++)
        w[j] = (uint32_t)sh[lc][sub*8 + 2*j] | ((uint32_t)sh[lc][sub*8 + 2*j+1] << 16);
    *(uint4*)(g_vthf + (size_t)(col0 + lc)*NTOK + m0 + sub*8) = make_uint4(w[0], w[1], w[2], w[3]);
}

// ---------------- K5: BIG GEMM via warp HMMA (fp16 single-pass) -----------
#define TK    128
#define NCH   (GK/TK)      // 18
#define A0    0
#define A1    16384
#define B0_   32768
#define B1_   65536
#define STG   98304
#define SMEM_MMA (2*STG)   // 196608

__global__ void __launch_bounds__(512, 1) k_lamp_hmma() {
    extern __shared__ char smem[];
    uint32_t sb = smem_u32(smem);
    int t = threadIdx.x;
    int nbase = blockIdx.x * 8;

    int n_loc = t >> 6, mi = t & 63;
    int n = nbase + n_loc;
    int n_row = n / 48, n_col = n - n_row*48;
    bool even = !(t & 1);

    int wid = t >> 5, lane = t & 31;
    int wm = wid >> 2, wn = wid & 3;
    int lr = lane & 15, lc = (lane >> 4) * 16;

    float acc[2][8][4];
    #pragma unroll
    for (int i = 0; i < 2; i++)
        #pragma unroll
        for (int j = 0; j < 8; j++)
            #pragma unroll
            for (int q = 0; q < 4; q++) acc[i][j][q] = 0.f;

    uint4 ra[2], rb2[2];    // A prefetch: sub0, sub1

    auto ldgA = [&](int c) {
        int ma = c*TK + mi;
        int mr = ma / 48, mc2 = ma - mr*48;
        const uint4* p0 = (const uint4*)(g_Rh + (size_t)((mr - n_row + 47)*95 + (mc2 - n_col + 47)) * 16);
        ra[0] = p0[0]; ra[1] = p0[1];
        int mb = ma + 64;
        mr = mb / 48; mc2 = mb - mr*48;
        const uint4* p1 = (const uint4*)(g_Rh + (size_t)((mr - n_row + 47)*95 + (mc2 - n_col + 47)) * 16);
        rb2[0] = p1[0]; rb2[1] = p1[1];
    };
    auto stsA = [&](int p) {
        uint32_t cb = (uint32_t)(mi & 62) * 2;
        #pragma unroll
        for (int s = 0; s < 2; s++) {
            char* base = smem + p*STG + (s ? A1 : A0);
            const uint32_t* rr = (const uint32_t*)(s ? rb2 : ra);
            #pragma unroll
            for (int j = 0; j < 8; j++) {
                uint32_t got = __shfl_xor_sync(0xffffffffu, rr[j], 1);
                uint32_t a = even ? rr[j] : got;   // m-even data
                uint32_t b = even ? got   : rr[j]; // m-odd data
                if (even) {
                    uint32_t w0 = __byte_perm(a, b, 0x5410);    // k = 2j
                    uint32_t r0 = (uint32_t)(n_loc*16 + 2*j);
                    *(uint32_t*)(base + ((r0*128u + cb) ^ ((r0 & 7u) << 4))) = w0;
                } else {
                    uint32_t w1 = __byte_perm(a, b, 0x7632);    // k = 2j+1
                    uint32_t r1 = (uint32_t)(n_loc*16 + 2*j + 1);
                    *(uint32_t*)(base + ((r1*128u + cb) ^ ((r1 & 7u) << 4))) = w1;
                }
            }
        }
    };
    auto cpB = [&](int c, int p) {
        int m0 = c * TK;
        uint32_t sa = sb + p*STG;
        #pragma unroll
        for (int i = 0; i < 8; i++) {
            int idx = t*8 + i;                  // 4096 = 256 col x 2 sub x 8 ch
            uint32_t col = (uint32_t)(idx >> 4);
            uint32_t s   = (uint32_t)((idx >> 3) & 1);
            uint32_t ch  = (uint32_t)(idx & 7);
            uint32_t off = (col*128u + ch*16u) ^ ((col & 7u) << 4);
            cp16(sa + (s ? B1_ : B0_) + off,
                 (const char*)(g_vthf + (size_t)col*NTOK + m0 + s*64) + ch*16);
        }
    };

    // prologue
    ldgA(0);
    cpB(0, 0); CP_COMMIT();
    stsA(0);
    ldgA(1);
    cpB(1, 1); CP_COMMIT();
    CP_WAIT1();
    __syncthreads();

    int p = 0;
    for (int c = 0; c < NCH; c++) {
        uint32_t sa = sb + p*STG;
        #pragma unroll
        for (int kk = 0; kk < 8; kk++) {
            uint32_t abase = sa + (kk < 4 ? A0 : A1);
            uint32_t bbase = sa + (kk < 4 ? B0_ : B1_);
            uint32_t kb = (uint32_t)((kk & 3) * 32);
            uint32_t aa[8], bb[16];
            #pragma unroll
            for (int mf = 0; mf < 2; mf++) {
                uint32_t row = (uint32_t)(wm*32 + mf*16 + lr);
                uint32_t off = (row*128u + kb + (uint32_t)lc) ^ ((row & 7u) << 4);
                ldmx4(aa + mf*4, abase + off);
            }
            #pragma unroll
            for (int ng = 0; ng < 4; ng++) {
                uint32_t row = (uint32_t)(wn*64 + ng*16 + lr);
                uint32_t off = (row*128u + kb + (uint32_t)lc) ^ ((row & 7u) << 4);
                ldmx4(bb + ng*4, bbase + off);
            }
            #pragma unroll
            for (int mf = 0; mf < 2; mf++)
                #pragma unroll
                for (int nf = 0; nf < 8; nf++)
                    mma16816(acc[mf][nf], aa + mf*4, bb[(nf>>1)*4 + (nf&1)], bb[(nf>>1)*4 + (nf&1) + 2]);
        }
        if (c + 1 < NCH) stsA(1 - p);
        if (c + 2 < NCH) ldgA(c + 2);
        CP_WAIT0();
        __syncthreads();
        if (c + 2 < NCH) { cpB(c + 2, p); CP_COMMIT(); }
        p ^= 1;
    }

    #pragma unroll
    for (int mf = 0; mf < 2; mf++) {
        #pragma unroll
        for (int nf = 0; nf < 8; nf++) {
            int r0 = blockIdx.x*128 + wm*32 + mf*16 + (lane >> 2);
            int c0 = wn*64 + nf*8 + (lane & 3)*2;
            *(float2*)&g_lamp[(size_t)r0*256 + c0]     = make_float2(acc[mf][nf][0], acc[mf][nf][1]);
            *(float2*)&g_lamp[(size_t)(r0+8)*256 + c0] = make_float2(acc[mf][nf][2], acc[mf][nf][3]);
        }
    }
}

// ---------------- K3: softmax over m (coalesced, register-resident) --------
__global__ void k_softmax() {
    __shared__ float red[256];
    int bk = blockIdx.x, t = threadIdx.x;
    const float* src = g_kT + (size_t)bk*NTOK;
    float r[9];
    #pragma unroll
    for (int i = 0; i < 9; i++) r[i] = src[t + i*256];
    float mx = r[0];
    #pragma unroll
    for (int i = 1; i < 9; i++) mx = fmaxf(mx, r[i]);
    red[t] = mx; __syncthreads();
    for (int s = 128; s > 0; s >>= 1) { if (t < s) red[t] = fmaxf(red[t], red[t+s]); __syncthreads(); }
    mx = red[0]; __syncthreads();
    float sum = 0.f;
    #pragma unroll
    for (int i = 0; i < 9; i++) { r[i] = expf(r[i] - mx); sum += r[i]; }
    red[t] = sum; __syncthreads();
    for (int s = 128; s > 0; s >>= 1) { if (t < s) red[t] += red[t+s]; __syncthreads(); }
    float inv = 1.0f / red[0];
    float* dst = g_ksm + (size_t)bk*NTOK;
    #pragma unroll
    for (int i = 0; i < 9; i++) dst[t + i*256] = r[i] * inv;
}

// ---------------- K4: content lambda lamc ---------------------------------
__global__ void k_lamc_part() {
    __shared__ float Ks[16*128];
    __shared__ float Vs[128*32];
    int b = blockIdx.x / 18, mc = blockIdx.x - b*18;
    int m0 = mc * 128;
    int t = threadIdx.x;
    for (int i = t; i < 2048; i += 512) { int k = i>>7, mm = i&127; Ks[i] = g_ksm[(size_t)(b*16+k)*NTOK + m0+mm]; }
    for (int i = t; i < 4096; i += 512) { int mm = i>>5, v = i&31;  Vs[i] = g_vt[(size_t)(m0+mm)*256 + b*32 + v]; }
    __syncthreads();
    int k = t >> 5, v = t & 31;
    float acc = 0.f;
    #pragma unroll 8
    for (int mm = 0; mm < 128; mm++) acc += Ks[k*128+mm] * Vs[mm*32+v];
    g_lamc_part[(size_t)blockIdx.x*512 + t] = acc;
}
__global__ void k_lamc_red() {
    int b = blockIdx.x, t = threadIdx.x;
    float s = 0.f;
    for (int mc = 0; mc < 18; mc++) s += g_lamc_part[(size_t)(b*18+mc)*512 + t];
    g_lamc[b*512 + t] = s;
}

// ---------------- K6: consumers -> appearance + motion --------------------
__global__ void k_out(const float* __restrict__ cor,
                      const float* __restrict__ Wce, const float* __restrict__ bce,
                      const float* __restrict__ Wcc, const float* __restrict__ Wmp,
                      const float* __restrict__ bmp,
                      float* __restrict__ app, float* __restrict__ mot) {
    extern __shared__ float sm[];
    float* WccT  = sm;
    float* WmpT  = sm + 8320;
    float* WceS  = sm + 16576;
    float* bceS  = sm + 16704;
    float* bmpS  = sm + 16768;
    float* lamcS = sm + 16896;
    float* grp   = sm + 17408;
    int t = threadIdx.x;
    int g = t >> 7, t1 = t & 127;
    int b = (blockIdx.x * 8) / NTOK;

    for (int i = t; i < 8192; i += 256) { int o = i>>7, c = i&127; WccT[c*65 + o]  = Wcc[i]; }
    for (int i = t; i < 8192; i += 256) { int o = i>>6, c = i&63;  WmpT[c*129 + o] = Wmp[i]; }
    if (t < 128) WceS[t] = Wce[t];
    if (t < 64)  bceS[t] = bce[t];
    if (t < 128) bmpS[t] = bmp[t];
    for (int i = t; i < 512; i += 256) lamcS[i] = g_lamc[b*512 + i];
    __syncthreads();

    float* Qn   = grp + g*832;
    float* ceS  = Qn + 64;
    float* Ltot = ceS + 64;
    float* crow = Ltot + 512;
    float* dif  = crow + 128;

    for (int it = 0; it < 4; it++) {
        int row = blockIdx.x*8 + it*2 + g;
        int n = row - b*NTOK;
        for (int i = t1; i < 512; i += 128) {
            int k = i >> 5, v = i & 31;
            Ltot[i] = lamcS[i] + g_lamp[(size_t)(n*16 + k)*256 + b*32 + v];
        }
        if (t1 < 64) {
            Qn[t1] = g_q[(size_t)row*64 + t1] * g_qaff[t1] + g_qaff[64+t1];
        } else {
            int o = t1 - 64;
            float c0 = cor[(size_t)row*2], c1 = cor[(size_t)row*2 + 1];
            ceS[o] = c0*WceS[o*2] + c1*WceS[o*2+1] + bceS[o];
        }
        __syncthreads();
        {
            int h = t1 >> 5, v = t1 & 31;
            float y = 0.f, cr = 0.f;
            #pragma unroll
            for (int k = 0; k < 16; k++) {
                float a = Ltot[k*32 + v];
                y  += Qn[h*16 + k]  * a;
                cr += ceS[h*16 + k] * a;
            }
            app[(size_t)row*128 + t1] = y;
            crow[t1] = cr;
        }
        __syncthreads();
        if (t1 < 64) {
            float s = 0.f;
            #pragma unroll 4
            for (int c = 0; c < 128; c++) s += crow[c] * WccT[c*65 + t1];
            dif[t1] = s - ceS[t1];
        }
        __syncthreads();
        {
            float s = bmpS[t1];
            #pragma unroll 4
            for (int c = 0; c < 64; c++) s += dif[c] * WmpT[c*129 + t1];
            mot[(size_t)row*128 + t1] = s;
        }
        __syncthreads();
    }
}

// ---------------- launch ---------------------------------------------------
extern "C" void kernel_launch(void* const* d_in, const int* in_sizes, int n_in,
                              void* d_out, int out_size) {
    const float* x   = (const float*)d_in[0];
    const float* cor = (const float*)d_in[1];
    const float* Wq  = (const float*)d_in[2];
    const float* Wk  = (const float*)d_in[3];
    const float* Wv  = (const float*)d_in[4];
    const float* Wce = (const float*)d_in[5];
    const float* bce = (const float*)d_in[6];
    const float* Wcc = (const float*)d_in[7];
    const float* Wmp = (const float*)d_in[8];
    const float* bmp = (const float*)d_in[9];
    const float* gq  = (const float*)d_in[10];
    const float* bq  = (const float*)d_in[11];
    const float* gv  = (const float*)d_in[12];
    const float* bv  = (const float*)d_in[13];
    const float* rpe = (const float*)d_in[14];
    float* app = (float*)d_out;
    float* mot = app + (size_t)NROW*128;

    cudaFuncSetAttribute(k_out, cudaFuncAttributeMaxDynamicSharedMemorySize, 19072*4);
    cudaFuncSetAttribute(k_lamp_hmma, cudaFuncAttributeMaxDynamicSharedMemorySize, SMEM_MMA);

    k_proj<<<853, 256>>>(x, Wq, Wk, Wv, rpe);     // #1 (incl. R fp16 convert)
    k_affine<<<1, 128>>>(gq, bq, gv, bv);         // #2
    k_vt<<<288, 256>>>();                         // #3
    k_lamp_hmma<<<288, 512, SMEM_MMA>>>();        // #4  <- profiled slot
    k_softmax<<<128, 256>>>();                    // #5
    k_lamc_part<<<144, 512>>>();                  // #6
    k_lamc_red<<<8, 512>>>();                     // #7
    k_out<<<NROW/8, 256, 19072*4>>>(cor, Wce, bce, Wcc, Wmp, bmp, app, mot);  // #8
}

// round 8
// speedup vs baseline: 3.3419x; 1.0434x over previous
#include <cuda_runtime.h>
#include <cuda_fp16.h>
#include <math.h>
#include <stdint.h>

#define B_    8
#define NTOK  2304
#define NROW  (B_*NTOK)      // 18432
#define HK    64
#define KD    16
#define VD    32
#define GM    (NTOK*KD)      // 36864
#define GN    (B_*VD)        // 256
#define GK    NTOK           // 2304
#define RTAB  (95*95*16)     // 144400

// ---------------- scratch (device globals; no allocations) ----------------
__device__ __align__(256) float g_q[(size_t)NROW*HK];
__device__ __align__(256) float g_kT[(size_t)B_*KD*NTOK];
__device__ __align__(256) float g_v[(size_t)NROW*VD];
__device__ __align__(256) float g_ksm[(size_t)B_*KD*NTOK];
__device__ __align__(256) float g_vt[(size_t)NTOK*GN];
__device__ __align__(256) unsigned short g_vthf[(size_t)GN*NTOK];      // [(b,v)][m] fp16
__device__ __align__(256) unsigned short g_Rh[RTAB];                   // rel-pos fp16
__device__ __align__(256) float g_part[288*224];
__device__ __align__(256) float g_lamc_part[(size_t)144*KD*VD];
__device__ __align__(256) float g_lamc[(size_t)B_*KD*VD];
__device__ __align__(256) float g_qaff[2*HK];
__device__ __align__(256) float g_vaff[2*VD];
__device__ __align__(256) float g_lamp[(size_t)GM*GN];

// ---------------- portable PTX helpers ------------------------------------
__device__ __forceinline__ uint32_t smem_u32(const void* p) {
    uint32_t a;
    asm("{ .reg .u64 t; cvta.to.shared.u64 t, %1; cvt.u32.u64 %0, t; }" : "=r"(a) : "l"(p));
    return a;
}
__device__ __forceinline__ void ldmx4(uint32_t* r, uint32_t addr) {
    asm volatile("ldmatrix.sync.aligned.m8n8.x4.shared.b16 {%0,%1,%2,%3}, [%4];"
        : "=r"(r[0]), "=r"(r[1]), "=r"(r[2]), "=r"(r[3]) : "r"(addr));
}
__device__ __forceinline__ void mma16816(float* d, const uint32_t* a, uint32_t b0, uint32_t b1) {
    asm volatile("mma.sync.aligned.m16n8k16.row.col.f32.f16.f16.f32 "
        "{%0,%1,%2,%3}, {%4,%5,%6,%7}, {%8,%9}, {%0,%1,%2,%3};"
        : "+f"(d[0]), "+f"(d[1]), "+f"(d[2]), "+f"(d[3])
        : "r"(a[0]), "r"(a[1]), "r"(a[2]), "r"(a[3]), "r"(b0), "r"(b1));
}
__device__ __forceinline__ void cp16(uint32_t saddr, const void* g) {
    asm volatile("cp.async.cg.shared.global [%0], [%1], 16;" :: "r"(saddr), "l"(g));
}
#define CP_COMMIT() asm volatile("cp.async.commit_group;" ::: "memory")
#define CP_WAIT1()  asm volatile("cp.async.wait_group 1;" ::: "memory")
#define CP_WAIT0()  asm volatile("cp.async.wait_group 0;" ::: "memory")

// ---------------- K1: tiled q/k/v 1x1 conv + BN partials + R convert ------
__global__ void __launch_bounds__(256) k_proj(const float* __restrict__ x,
                       const float* __restrict__ Wq,
                       const float* __restrict__ Wk,
                       const float* __restrict__ Wv,
                       const float* __restrict__ R) {
    if (blockIdx.x >= 288) {
        int i = (blockIdx.x - 288)*256 + threadIdx.x;
        if (i < RTAB) g_Rh[i] = __half_as_ushort(__float2half_rn(R[i]));
        return;
    }
    __shared__ float Xs[64*33];
    __shared__ float Ws2[112*33];
    __shared__ float red[16*112];
    int t = threadIdx.x;
    int ty = t >> 4, tx = t & 15;
    int row0 = blockIdx.x * 64;
    int bs = blockIdx.x / 36;
    float acc[4][7];
    #pragma unroll
    for (int i = 0; i < 4; i++)
        #pragma unroll
        for (int j = 0; j < 7; j++) acc[i][j] = 0.f;

    for (int k0 = 0; k0 < 128; k0 += 32) {
        for (int e = t; e < 2048; e += 256) {
            int r = e >> 5, k = e & 31;
            Xs[r*33 + k] = x[(size_t)(row0+r)*128 + k0 + k];
        }
        for (int e = t; e < 3584; e += 256) {
            int o = e >> 5, k = e & 31;
            float w;
            if (o < 64)      w = Wq[o*128 + k0 + k];
            else if (o < 80) w = Wk[(o-64)*128 + k0 + k];
            else             w = Wv[(o-80)*128 + k0 + k];
            Ws2[o*33 + k] = w;
        }
        __syncthreads();
        #pragma unroll 8
        for (int kk = 0; kk < 32; kk++) {
            float a[4], b[7];
            #pragma unroll
            for (int i = 0; i < 4; i++) a[i] = Xs[(ty*4+i)*33 + kk];
            #pragma unroll
            for (int j = 0; j < 7; j++) b[j] = Ws2[(tx*7+j)*33 + kk];
            #pragma unroll
            for (int i = 0; i < 4; i++)
                #pragma unroll
                for (int j = 0; j < 7; j++) acc[i][j] += a[i]*b[j];
        }
        __syncthreads();
    }

    int db = (bs + 4) & 7;
    #pragma unroll
    for (int i = 0; i < 4; i++) {
        int row = row0 + ty*4 + i;
        int n = row - bs*NTOK;
        #pragma unroll
        for (int j = 0; j < 7; j++) {
            int o = tx*7 + j;
            float val = acc[i][j];
            if (o < 64)       g_q[(size_t)row*64 + o] = val;
            else if (o < 80)  g_kT[(size_t)(db*16 + o-64)*NTOK + n] = val;
            else              g_v[((size_t)db*NTOK + n)*32 + (o-80)] = val;
        }
    }
    float ps[7], pq[7];
    #pragma unroll
    for (int j = 0; j < 7; j++) {
        ps[j] = acc[0][j]+acc[1][j]+acc[2][j]+acc[3][j];
        pq[j] = acc[0][j]*acc[0][j]+acc[1][j]*acc[1][j]+acc[2][j]*acc[2][j]+acc[3][j]*acc[3][j];
    }
    #pragma unroll
    for (int j = 0; j < 7; j++) red[ty*112 + tx*7 + j] = ps[j];
    __syncthreads();
    if (t < 112) {
        float s = 0.f;
        #pragma unroll
        for (int yy = 0; yy < 16; yy++) s += red[yy*112 + t];
        g_part[blockIdx.x*224 + t] = s;
    }
    __syncthreads();
    #pragma unroll
    for (int j = 0; j < 7; j++) red[ty*112 + tx*7 + j] = pq[j];
    __syncthreads();
    if (t < 112) {
        float s = 0.f;
        #pragma unroll
        for (int yy = 0; yy < 16; yy++) s += red[yy*112 + t];
        g_part[blockIdx.x*224 + 112 + t] = s;
    }
}

// ---------------- K2: reduce BN partials -> affine -------------------------
__global__ void k_affine(const float* __restrict__ gq, const float* __restrict__ bq,
                         const float* __restrict__ gv, const float* __restrict__ bv) {
    int t = threadIdx.x;
    if (t >= 112 || (t >= 64 && t < 80)) return;
    float s = 0.f, s2 = 0.f;
    for (int i = 0; i < 288; i++) {
        s  += g_part[i*224 + t];
        s2 += g_part[i*224 + 112 + t];
    }
    float mu  = s / (float)NROW;
    float var = s2 / (float)NROW - mu*mu;
    if (t < 64) {
        float sc = gq[t] * rsqrtf(var + 1e-5f);
        g_qaff[t] = sc; g_qaff[64+t] = bq[t] - mu*sc;
    } else {
        int c = t - 80;
        float sc = gv[c] * rsqrtf(var + 1e-5f);
        g_vaff[c] = sc; g_vaff[32+c] = bv[c] - mu*sc;
    }
}

// ---------------- K3b: BN(V) -> fp32 [m][col] + fp16 [col][m] -------------
__global__ void k_vt() {
    __shared__ unsigned short sh[64][33];
    int t = threadIdx.x;
    int cg = blockIdx.x & 3, mg = blockIdx.x >> 2;   // 4 x 72
    int col0 = cg*64, m0 = mg*32;
    for (int e = t; e < 2048; e += 256) {
        int lm = e >> 6, lc = e & 63;
        int col = col0 + lc;
        int b = col >> 5, v = col & 31;
        int m = m0 + lm;
        float xv = g_v[((size_t)b*NTOK + m)*32 + v] * g_vaff[v] + g_vaff[32+v];
        g_vt[(size_t)m*256 + col] = xv;
        sh[lc][lm] = __half_as_ushort(__float2half_rn(xv));
    }
    __syncthreads();
    int lc = t >> 2, sub = t & 3;
    uint32_t w[4];
    #pragma unroll
    for (int j = 0; j < 4; j++)
        w[j] = (uint32_t)sh[lc][sub*8 + 2*j] | ((uint32_t)sh[lc][sub*8 + 2*j+1] << 16);
    *(uint4*)(g_vthf + (size_t)(col0 + lc)*NTOK + m0 + sub*8) = make_uint4(w[0], w[1], w[2], w[3]);
}

// ---------------- K5: BIG GEMM via warp HMMA (fp16, 2 CTAs/SM) ------------
// CTA: 256 thr, 8 warps (4x2), tile M=128 x N=128, TK=64, double-buffered.
#define TK    64
#define NCH   (GK/TK)      // 36
#define AOFF  0            // 16 KB: 128 rows x 128 B
#define BOFF  16384        // 16 KB: 128 cols x 128 B
#define STG   32768
#define SMEM_MMA (2*STG)   // 65536

__global__ void __launch_bounds__(256, 2) k_lamp_hmma() {
    extern __shared__ char smem[];
    uint32_t sb = smem_u32(smem);
    int t = threadIdx.x;
    int nbase = blockIdx.y * 8;
    int col0  = blockIdx.x * 128;

    // A-gather role: one m-pair for one n_loc, all 16 k
    int n_loc = t >> 5, mi2 = t & 31;
    int n = nbase + n_loc;
    int n_row = n / 48, n_col = n - n_row*48;

    // compute role
    int wid = t >> 5, lane = t & 31;
    int wm = wid >> 1, wn = wid & 1;
    int lr = lane & 15, lc2 = (lane >> 4) * 16;   // byte offset within 32B k-step

    float acc[2][8][4];
    #pragma unroll
    for (int i = 0; i < 2; i++)
        #pragma unroll
        for (int j = 0; j < 8; j++)
            #pragma unroll
            for (int q = 0; q < 4; q++) acc[i][j][q] = 0.f;

    uint4 ra0, ra1, rb0, rb1;   // A prefetch: m-even (ra), m-odd (rb)

    auto ldgA = [&](int c) {
        int ma = c*TK + 2*mi2;
        int mr = ma / 48, mc2 = ma - mr*48;
        const uint4* pa = (const uint4*)(g_Rh + (size_t)((mr - n_row + 47)*95 + (mc2 - n_col + 47)) * 16);
        ra0 = pa[0]; ra1 = pa[1];
        int mb = ma + 1;
        mr = mb / 48; mc2 = mb - mr*48;
        const uint4* pb = (const uint4*)(g_Rh + (size_t)((mr - n_row + 47)*95 + (mc2 - n_col + 47)) * 16);
        rb0 = pb[0]; rb1 = pb[1];
    };
    auto stsA = [&](int p) {
        char* base = smem + p*STG + AOFF;
        uint32_t aw[8] = {ra0.x,ra0.y,ra0.z,ra0.w,ra1.x,ra1.y,ra1.z,ra1.w};
        uint32_t bw[8] = {rb0.x,rb0.y,rb0.z,rb0.w,rb1.x,rb1.y,rb1.z,rb1.w};
        uint32_t cb = (uint32_t)mi2 * 4;
        #pragma unroll
        for (int i = 0; i < 8; i++) {
            uint32_t w0 = __byte_perm(aw[i], bw[i], 0x5410);   // k = 2i
            uint32_t w1 = __byte_perm(aw[i], bw[i], 0x7632);   // k = 2i+1
            uint32_t r0 = (uint32_t)(n_loc*16 + 2*i);
            uint32_t r1 = r0 + 1;
            *(uint32_t*)(base + ((r0*128u + cb) ^ ((r0 & 7u) << 4))) = w0;
            *(uint32_t*)(base + ((r1*128u + cb) ^ ((r1 & 7u) << 4))) = w1;
        }
    };
    auto cpB = [&](int c, int p) {
        int m0 = c * TK;
        uint32_t sa = sb + p*STG + BOFF;
        #pragma unroll
        for (int i = 0; i < 4; i++) {
            int idx = t*4 + i;                 // 1024 = 128 cols x 8 chunks
            uint32_t col = (uint32_t)(idx >> 3), ch = (uint32_t)(idx & 7);
            uint32_t off = (col*128u + ch*16u) ^ ((col & 7u) << 4);
            cp16(sa + off, g_vthf + (size_t)(col0 + col)*NTOK + m0 + ch*8);
        }
    };

    // prologue
    ldgA(0); cpB(0, 0); CP_COMMIT(); stsA(0);
    ldgA(1); cpB(1, 1); CP_COMMIT();
    CP_WAIT1();
    __syncthreads();

    int p = 0;
    for (int c = 0; c < NCH; c++) {
        uint32_t sa = sb + p*STG;
        #pragma unroll
        for (int kk = 0; kk < 4; kk++) {
            uint32_t kb = (uint32_t)(kk * 32);
            uint32_t aa[8], bb[16];
            #pragma unroll
            for (int mf = 0; mf < 2; mf++) {
                uint32_t row = (uint32_t)(wm*32 + mf*16 + lr);
                uint32_t off = (row*128u + kb + (uint32_t)lc2) ^ ((row & 7u) << 4);
                ldmx4(aa + mf*4, sa + AOFF + off);
            }
            #pragma unroll
            for (int ng = 0; ng < 4; ng++) {
                uint32_t row = (uint32_t)(wn*64 + ng*16 + lr);
                uint32_t off = (row*128u + kb + (uint32_t)lc2) ^ ((row & 7u) << 4);
                ldmx4(bb + ng*4, sa + BOFF + off);
            }
            #pragma unroll
            for (int mf = 0; mf < 2; mf++)
                #pragma unroll
                for (int nf = 0; nf < 8; nf++)
                    mma16816(acc[mf][nf], aa + mf*4, bb[(nf>>1)*4 + (nf&1)], bb[(nf>>1)*4 + (nf&1) + 2]);
        }
        if (c + 1 < NCH) stsA(1 - p);
        if (c + 2 < NCH) ldgA(c + 2);
        CP_WAIT0();
        __syncthreads();
        if (c + 2 < NCH) { cpB(c + 2, p); CP_COMMIT(); }
        p ^= 1;
    }

    // epilogue
    #pragma unroll
    for (int mf = 0; mf < 2; mf++) {
        #pragma unroll
        for (int nf = 0; nf < 8; nf++) {
            int r0 = blockIdx.y*128 + wm*32 + mf*16 + (lane >> 2);
            int c0 = col0 + wn*64 + nf*8 + (lane & 3)*2;
            *(float2*)&g_lamp[(size_t)r0*256 + c0]     = make_float2(acc[mf][nf][0], acc[mf][nf][1]);
            *(float2*)&g_lamp[(size_t)(r0+8)*256 + c0] = make_float2(acc[mf][nf][2], acc[mf][nf][3]);
        }
    }
}

// ---------------- K3: softmax over m ---------------------------------------
__global__ void k_softmax() {
    __shared__ float red[256];
    int bk = blockIdx.x, t = threadIdx.x;
    const float* src = g_kT + (size_t)bk*NTOK;
    float r[9];
    #pragma unroll
    for (int i = 0; i < 9; i++) r[i] = src[t + i*256];
    float mx = r[0];
    #pragma unroll
    for (int i = 1; i < 9; i++) mx = fmaxf(mx, r[i]);
    red[t] = mx; __syncthreads();
    for (int s = 128; s > 0; s >>= 1) { if (t < s) red[t] = fmaxf(red[t], red[t+s]); __syncthreads(); }
    mx = red[0]; __syncthreads();
    float sum = 0.f;
    #pragma unroll
    for (int i = 0; i < 9; i++) { r[i] = expf(r[i] - mx); sum += r[i]; }
    red[t] = sum; __syncthreads();
    for (int s = 128; s > 0; s >>= 1) { if (t < s) red[t] += red[t+s]; __syncthreads(); }
    float inv = 1.0f / red[0];
    float* dst = g_ksm + (size_t)bk*NTOK;
    #pragma unroll
    for (int i = 0; i < 9; i++) dst[t + i*256] = r[i] * inv;
}

// ---------------- K4: content lambda lamc ---------------------------------
__global__ void k_lamc_part() {
    __shared__ float Ks[16*128];
    __shared__ float Vs[128*32];
    int b = blockIdx.x / 18, mc = blockIdx.x - b*18;
    int m0 = mc * 128;
    int t = threadIdx.x;
    for (int i = t; i < 2048; i += 512) { int k = i>>7, mm = i&127; Ks[i] = g_ksm[(size_t)(b*16+k)*NTOK + m0+mm]; }
    for (int i = t; i < 4096; i += 512) { int mm = i>>5, v = i&31;  Vs[i] = g_vt[(size_t)(m0+mm)*256 + b*32 + v]; }
    __syncthreads();
    int k = t >> 5, v = t & 31;
    float acc = 0.f;
    #pragma unroll 8
    for (int mm = 0; mm < 128; mm++) acc += Ks[k*128+mm] * Vs[mm*32+v];
    g_lamc_part[(size_t)blockIdx.x*512 + t] = acc;
}
__global__ void k_lamc_red() {
    int b = blockIdx.x, t = threadIdx.x;
    float s = 0.f;
    for (int mc = 0; mc < 18; mc++) s += g_lamc_part[(size_t)(b*18+mc)*512 + t];
    g_lamc[b*512 + t] = s;
}

// ---------------- K6: consumers (32 rows per block) -----------------------
__global__ void k_out(const float* __restrict__ cor,
                      const float* __restrict__ Wce, const float* __restrict__ bce,
                      const float* __restrict__ Wcc, const float* __restrict__ Wmp,
                      const float* __restrict__ bmp,
                      float* __restrict__ app, float* __restrict__ mot) {
    extern __shared__ float sm[];
    float* WccT  = sm;
    float* WmpT  = sm + 8320;
    float* WceS  = sm + 16576;
    float* bceS  = sm + 16704;
    float* bmpS  = sm + 16768;
    float* lamcS = sm + 16896;
    float* grp   = sm + 17408;
    int t = threadIdx.x;
    int g = t >> 7, t1 = t & 127;
    int b = (blockIdx.x * 32) / NTOK;     // 72 blocks per batch

    for (int i = t; i < 8192; i += 256) { int o = i>>7, c = i&127; WccT[c*65 + o]  = Wcc[i]; }
    for (int i = t; i < 8192; i += 256) { int o = i>>6, c = i&63;  WmpT[c*129 + o] = Wmp[i]; }
    if (t < 128) WceS[t] = Wce[t];
    if (t < 64)  bceS[t] = bce[t];
    if (t < 128) bmpS[t] = bmp[t];
    for (int i = t; i < 512; i += 256) lamcS[i] = g_lamc[b*512 + i];
    __syncthreads();

    float* Qn   = grp + g*832;
    float* ceS  = Qn + 64;
    float* Ltot = ceS + 64;
    float* crow = Ltot + 512;
    float* dif  = crow + 128;

    for (int it = 0; it < 16; it++) {
        int row = blockIdx.x*32 + it*2 + g;
        int n = row - b*NTOK;
        for (int i = t1; i < 512; i += 128) {
            int k = i >> 5, v = i & 31;
            Ltot[i] = lamcS[i] + g_lamp[(size_t)(n*16 + k)*256 + b*32 + v];
        }
        if (t1 < 64) {
            Qn[t1] = g_q[(size_t)row*64 + t1] * g_qaff[t1] + g_qaff[64+t1];
        } else {
            int o = t1 - 64;
            float c0 = cor[(size_t)row*2], c1 = cor[(size_t)row*2 + 1];
            ceS[o] = c0*WceS[o*2] + c1*WceS[o*2+1] + bceS[o];
        }
        __syncthreads();
        {
            int h = t1 >> 5, v = t1 & 31;
            float y = 0.f, cr = 0.f;
            #pragma unroll
            for (int k = 0; k < 16; k++) {
                float a = Ltot[k*32 + v];
                y  += Qn[h*16 + k]  * a;
                cr += ceS[h*16 + k] * a;
            }
            app[(size_t)row*128 + t1] = y;
            crow[t1] = cr;
        }
        __syncthreads();
        if (t1 < 64) {
            float s = 0.f;
            #pragma unroll 4
            for (int c = 0; c < 128; c++) s += crow[c] * WccT[c*65 + t1];
            dif[t1] = s - ceS[t1];
        }
        __syncthreads();
        {
            float s = bmpS[t1];
            #pragma unroll 4
            for (int c = 0; c < 64; c++) s += dif[c] * WmpT[c*129 + t1];
            mot[(size_t)row*128 + t1] = s;
        }
        __syncthreads();
    }
}

// ---------------- launch ---------------------------------------------------
extern "C" void kernel_launch(void* const* d_in, const int* in_sizes, int n_in,
                              void* d_out, int out_size) {
    const float* x   = (const float*)d_in[0];
    const float* cor = (const float*)d_in[1];
    const float* Wq  = (const float*)d_in[2];
    const float* Wk  = (const float*)d_in[3];
    const float* Wv  = (const float*)d_in[4];
    const float* Wce = (const float*)d_in[5];
    const float* bce = (const float*)d_in[6];
    const float* Wcc = (const float*)d_in[7];
    const float* Wmp = (const float*)d_in[8];
    const float* bmp = (const float*)d_in[9];
    const float* gq  = (const float*)d_in[10];
    const float* bq  = (const float*)d_in[11];
    const float* gv  = (const float*)d_in[12];
    const float* bv  = (const float*)d_in[13];
    const float* rpe = (const float*)d_in[14];
    float* app = (float*)d_out;
    float* mot = app + (size_t)NROW*128;

    cudaFuncSetAttribute(k_out, cudaFuncAttributeMaxDynamicSharedMemorySize, 19072*4);
    cudaFuncSetAttribute(k_lamp_hmma, cudaFuncAttributeMaxDynamicSharedMemorySize, SMEM_MMA);

    k_proj<<<853, 256>>>(x, Wq, Wk, Wv, rpe);        // #1
    k_affine<<<1, 128>>>(gq, bq, gv, bv);            // #2
    k_vt<<<288, 256>>>();                            // #3
    k_lamp_hmma<<<dim3(2, 288), 256, SMEM_MMA>>>();  // #4  <- profiled slot
    k_softmax<<<128, 256>>>();                       // #5
    k_lamc_part<<<144, 512>>>();                     // #6
    k_lamc_red<<<8, 512>>>();                        // #7
    k_out<<<576, 256, 19072*4>>>(cor, Wce, bce, Wcc, Wmp, bmp, app, mot);  // #8
}